// round 6
// baseline (speedup 1.0000x reference)
#include <cuda_runtime.h>
#include <cuda_fp16.h>
#include <math.h>

// ---------------- scratch (no allocation allowed) ----------------
__device__ __half g_hs[6400000];   // 50000 x 128 (row stride 128 halves = 256B aligned)
__device__ float  g_acc[5000000];  // 50000 x 100 fp32 (reused across layers)
__device__ float  g_dinv[50048];
__device__ int    g_cnt[50048];
__device__ int    g_rowptr[50049];
__device__ int    g_off[50049];
__device__ int    g_adj[800064];
__device__ float  g_partials[512];
__device__ float  g_norm2;

// ---------------- prep: zero counters + ||x||^2 partial sums ----------------
__global__ void prep_kernel(const float* __restrict__ x, long n, int N) {
    int gs = gridDim.x * blockDim.x;
    for (int i = blockIdx.x * blockDim.x + threadIdx.x; i < N; i += gs) g_cnt[i] = 0;
    float s = 0.f;
    for (long i = (long)blockIdx.x * blockDim.x + threadIdx.x; i < n; i += gs) {
        float v = x[i];
        s += v * v;
    }
    __shared__ float sm[256];
    sm[threadIdx.x] = s;
    __syncthreads();
    for (int o = 128; o > 0; o >>= 1) {
        if (threadIdx.x < o) sm[threadIdx.x] += sm[threadIdx.x + o];
        __syncthreads();
    }
    if (threadIdx.x == 0) g_partials[blockIdx.x] = sm[0];
}

__global__ void hist_kernel(const int* __restrict__ dst, int E) {
    int i = blockIdx.x * blockDim.x + threadIdx.x;
    if (i < E) atomicAdd(&g_cnt[dst[i]], 1);
}

// ---------------- single-block fused scan: rowptr/off/dinv + norm2 finalize ----------------
__global__ void __launch_bounds__(1024)
scan_one_kernel(int N, int E) {
    __shared__ float fm[512];
    __shared__ int   sm[1024];
    int t = threadIdx.x;

    // finalize norm2 from 512 partials
    if (t < 512) fm[t] = g_partials[t];
    __syncthreads();
    for (int o = 256; o > 0; o >>= 1) {
        if (t < o) fm[t] += fm[t + o];
        __syncthreads();
    }
    if (t == 0) g_norm2 = fm[0];

    // per-thread serial sum over its chunk
    int per = (N + 1023) / 1024;
    int start = t * per;
    int stop = min(start + per, N);
    int s = 0;
    for (int i = start; i < stop; i++) s += g_cnt[i];
    sm[t] = s;
    __syncthreads();
    // Hillis-Steele inclusive scan over 1024 thread sums
    for (int o = 1; o < 1024; o <<= 1) {
        int v = (t >= o) ? sm[t - o] : 0;
        __syncthreads();
        sm[t] += v;
        __syncthreads();
    }
    int run = sm[t] - s;  // exclusive base for this thread's chunk
    for (int i = start; i < stop; i++) {
        int c = g_cnt[i];
        g_rowptr[i] = run;
        g_off[i] = run;
        g_dinv[i] = rsqrtf((float)(c + 1));  // +1 self-loop
        run += c;
    }
    if (t == 1023) g_rowptr[N] = E;
}

__global__ void fill_kernel(const int* __restrict__ src, const int* __restrict__ dst, int E) {
    int i = blockIdx.x * blockDim.x + threadIdx.x;
    if (i < E) {
        int pos = atomicAdd(&g_off[dst[i]], 1);
        g_adj[pos] = src[i];
    }
}

// ---------------- GEMM: hs = fp16( (out_dinv? dinv[row]:1) * ((X + bin) @ W) ) ----------------
// hs row stride = 128 halves.  [R2/R5-proven 128row/256thr config]
__global__ void __launch_bounds__(256)
gemm_kernel(const float* __restrict__ X, const float* __restrict__ W,
            const float* __restrict__ bin, int out_dinv,
            __half* __restrict__ hs, int N) {
    extern __shared__ float smem[];
    float* sW = smem;          // 10000 floats
    float* sX = smem + 10000;  // 128*100 = 12800 floats
    int tid = threadIdx.x;
    int row0 = blockIdx.x * 128;

    for (int i = tid; i < 2500; i += 256)
        ((float4*)sW)[i] = __ldg((const float4*)W + i);
    for (int i = tid; i < 3200; i += 256) {
        int r = i / 25, c = i - r * 25;
        int gr = row0 + r;
        float4 v = make_float4(0.f, 0.f, 0.f, 0.f);
        if (gr < N) {
            v = __ldg((const float4*)(X + (size_t)gr * 100) + c);
            if (bin) {
                float4 b = __ldg((const float4*)bin + c);
                v.x += b.x; v.y += b.y; v.z += b.z; v.w += b.w;
            }
        }
        *((float4*)(sX + r * 100) + c) = v;
    }
    __syncthreads();

    int tx = tid & 3, ty = tid >> 2;
    float a0[25], a1[25];
#pragma unroll
    for (int c = 0; c < 25; c++) { a0[c] = 0.f; a1[c] = 0.f; }
    const float* x0p = sX + ty * 100;
    const float* x1p = sX + (ty + 64) * 100;
    const float* wcol = sW + tx * 25;
#pragma unroll 2
    for (int k = 0; k < 100; k++) {
        float x0 = x0p[k];
        float x1 = x1p[k];
        const float* wr = wcol + k * 100;
#pragma unroll
        for (int c = 0; c < 25; c++) {
            float w = wr[c];
            a0[c] += x0 * w;
            a1[c] += x1 * w;
        }
    }

    int gr0 = row0 + ty;
    int gr1 = row0 + ty + 64;
    if (gr0 < N) {
        float s = out_dinv ? g_dinv[gr0] : 1.0f;
        __half* p = hs + (size_t)gr0 * 128 + tx * 25;
#pragma unroll
        for (int c = 0; c < 25; c++) p[c] = __float2half_rn(a0[c] * s);
    }
    if (gr1 < N) {
        float s = out_dinv ? g_dinv[gr1] : 1.0f;
        __half* p = hs + (size_t)gr1 * 128 + tx * 25;
#pragma unroll
        for (int c = 0; c < 25; c++) p[c] = __float2half_rn(a1[c] * s);
    }
}

// ---------------- CSR agg (warp per node, lanes 0..24 own 4 cols) ----------------
// PRESCALED=0 (layer0): acc = dinv_i*rsqrt(norm2) * (dinv_i*hs_i + sum_j dinv_j*hs_j)
// PRESCALED=1 (layer1): acc = hs_i + sum_j hs_j      (hs already dinv-scaled)
template<int PRESCALED>
__global__ void __launch_bounds__(256)
agg_kernel(const __half* __restrict__ hs, float* __restrict__ acc,
           const int* __restrict__ rowptr, const int* __restrict__ adj, int N) {
    int node = (blockIdx.x * 256 + threadIdx.x) >> 5;
    int lane = threadIdx.x & 31;
    if (node >= N) return;
    bool act = lane < 25;
    float di = g_dinv[node];

    float4 sum = make_float4(0.f, 0.f, 0.f, 0.f);
    if (act) {
        uint2 raw = __ldg((const uint2*)(hs + (size_t)node * 128) + lane);
        float2 f0 = __half22float2(*(const __half2*)&raw.x);
        float2 f1 = __half22float2(*(const __half2*)&raw.y);
        float sf = PRESCALED ? 1.0f : di;
        sum.x = sf * f0.x; sum.y = sf * f0.y;
        sum.z = sf * f1.x; sum.w = sf * f1.y;
    }

    int beg = rowptr[node];
    int end = rowptr[node + 1];
    for (int base = beg; base < end; base += 32) {
        int idx = base + lane;
        int my = 0; float md = 0.f;
        if (idx < end) {
            my = __ldg(adj + idx);
            if (!PRESCALED) md = g_dinv[my];
        }
        int cnt = min(32, end - base);
#pragma unroll 4
        for (int j = 0; j < cnt; j++) {
            int s = __shfl_sync(0xffffffffu, my, j);
            float d = PRESCALED ? 1.0f : __shfl_sync(0xffffffffu, md, j);
            if (act) {
                uint2 raw = __ldg((const uint2*)(hs + (size_t)s * 128) + lane);
                float2 f0 = __half22float2(*(const __half2*)&raw.x);
                float2 f1 = __half22float2(*(const __half2*)&raw.y);
                if (PRESCALED) {
                    sum.x += f0.x; sum.y += f0.y; sum.z += f1.x; sum.w += f1.y;
                } else {
                    sum.x += d * f0.x; sum.y += d * f0.y;
                    sum.z += d * f1.x; sum.w += d * f1.y;
                }
            }
        }
    }
    if (act) {
        if (!PRESCALED) {
            float os = di * rsqrtf(g_norm2);
            sum.x *= os; sum.y *= os; sum.z *= os; sum.w *= os;
        }
        *((float4*)(acc + (size_t)node * 100) + lane) = sum;
    }
}

// ---------------- MLP head: out[i] = relu((dinv_i*acc + cb1) @ W0 + b0) @ W1 + b1 ----------------
__global__ void head_kernel(const float* __restrict__ acc, const float* __restrict__ bconv,
                            const float* __restrict__ W0, const float* __restrict__ b0,
                            const float* __restrict__ W1, const float* __restrict__ b1,
                            float* __restrict__ out, int N) {
    __shared__ float xs[64 * 101];
    __shared__ float w0s[1000];
    __shared__ float w1s[10];
    __shared__ float b0s[10];
    __shared__ float bcs[100];
    int tid = threadIdx.x;
    int base = blockIdx.x * 64;

    for (int i = tid; i < 1000; i += 128) w0s[i] = W0[i];
    if (tid < 10) { w1s[tid] = W1[tid]; b0s[tid] = b0[tid]; }
    if (tid < 100) bcs[tid] = bconv[tid];
    __syncthreads();

    for (int i = tid; i < 6400; i += 128) {
        int r = i / 100, k = i - r * 100;
        int g = base + r;
        xs[r * 101 + k] = (g < N) ? (g_dinv[g] * acc[(size_t)g * 100 + k] + bcs[k]) : 0.f;
    }
    __syncthreads();

    if (tid < 64) {
        int g = base + tid;
        if (g < N) {
            float y[10];
#pragma unroll
            for (int j = 0; j < 10; j++) y[j] = b0s[j];
            const float* xr = xs + tid * 101;
            for (int k = 0; k < 100; k++) {
                float xv = xr[k];
#pragma unroll
                for (int j = 0; j < 10; j++) y[j] += xv * w0s[k * 10 + j];
            }
            float o = b1[0];
#pragma unroll
            for (int j = 0; j < 10; j++) o += fmaxf(y[j], 0.f) * w1s[j];
            out[g] = o;
        }
    }
}

extern "C" void kernel_launch(void* const* d_in, const int* in_sizes, int n_in,
                              void* d_out, int out_size) {
    const float* x   = (const float*)d_in[0];
    const int*   ei  = (const int*)d_in[1];
    const float* W0  = (const float*)d_in[2];
    const float* cb0 = (const float*)d_in[3];
    const float* W1  = (const float*)d_in[4];
    const float* cb1 = (const float*)d_in[5];
    const float* lW0 = (const float*)d_in[6];
    const float* lb0 = (const float*)d_in[7];
    const float* lW1 = (const float*)d_in[8];
    const float* lb1 = (const float*)d_in[9];
    float* out = (float*)d_out;

    int N = in_sizes[0] / 100;
    int E = in_sizes[1] / 2;
    const int* src = ei;
    const int* dst = ei + E;

    size_t gemm_smem = (10000 + 12800) * sizeof(float);  // 91.2 KB -> 2 blocks/SM
    cudaFuncSetAttribute(gemm_kernel,
                         cudaFuncAttributeMaxDynamicSharedMemorySize, (int)gemm_smem);

    __half* hs;
    float* acc;
    int *rowptr, *adj;
    cudaGetSymbolAddress((void**)&hs, g_hs);
    cudaGetSymbolAddress((void**)&acc, g_acc);
    cudaGetSymbolAddress((void**)&rowptr, g_rowptr);
    cudaGetSymbolAddress((void**)&adj, g_adj);

    cudaStream_t s2;
    cudaStreamCreateWithFlags(&s2, cudaStreamNonBlocking);
    cudaEvent_t ev0, ev1;
    cudaEventCreateWithFlags(&ev0, cudaEventDisableTiming);
    cudaEventCreateWithFlags(&ev1, cudaEventDisableTiming);

    cudaEventRecord(ev0, 0);
    cudaStreamWaitEvent(s2, ev0, 0);

    // branch B (default): gemm0 = raw x @ W0, no dependencies on branch A
    int gblocks = (N + 127) / 128;
    gemm_kernel<<<gblocks, 256, gemm_smem>>>(x, W0, nullptr, 0, hs, N);

    // branch A (s2): norm + degrees + CSR, fully overlapped with gemm0
    long n_elem = (long)N * 100;
    prep_kernel<<<512, 256, 0, s2>>>(x, n_elem, N);
    hist_kernel<<<(E + 255) / 256, 256, 0, s2>>>(dst, E);
    scan_one_kernel<<<1, 1024, 0, s2>>>(N, E);
    fill_kernel<<<(E + 255) / 256, 256, 0, s2>>>(src, dst, E);
    cudaEventRecord(ev1, s2);

    cudaStreamWaitEvent(0, ev1, 0);  // join

    int ablocks = (N + 7) / 8;  // warp per node
    agg_kernel<0><<<ablocks, 256>>>(hs, acc, rowptr, adj, N);
    gemm_kernel<<<gblocks, 256, gemm_smem>>>(acc, W1, cb0, 1, hs, N);
    agg_kernel<1><<<ablocks, 256>>>(hs, acc, rowptr, adj, N);
    head_kernel<<<(N + 63) / 64, 128>>>(acc, cb1, lW0, lb0, lW1, lb1, out, N);
}

// round 7
// speedup vs baseline: 1.4059x; 1.4059x over previous
#include <cuda_runtime.h>
#include <cuda_fp16.h>
#include <math.h>

// ---------------- scratch (no allocation allowed) ----------------
__device__ __half g_hs[6400000];   // 50000 x 128 (row stride 128 halves = 256B aligned)
__device__ float  g_acc[5000000];  // 50000 x 100 fp32 (reused across layers)
__device__ float  g_dinv[50048];
__device__ int    g_cnt[50048];
__device__ int    g_rowptr[50049];
__device__ int    g_off[50049];
__device__ int    g_adj[800064];
__device__ int    g_bsum[256];
__device__ float  g_partials[512];
__device__ float  g_norm2;

// ---------------- prep: zero counters + ||x||^2 partial sums ----------------
__global__ void prep_kernel(const float* __restrict__ x, long n, int N) {
    int gs = gridDim.x * blockDim.x;
    for (int i = blockIdx.x * blockDim.x + threadIdx.x; i < N; i += gs) g_cnt[i] = 0;
    float s = 0.f;
    for (long i = (long)blockIdx.x * blockDim.x + threadIdx.x; i < n; i += gs) {
        float v = x[i];
        s += v * v;
    }
    __shared__ float sm[256];
    sm[threadIdx.x] = s;
    __syncthreads();
    for (int o = 128; o > 0; o >>= 1) {
        if (threadIdx.x < o) sm[threadIdx.x] += sm[threadIdx.x + o];
        __syncthreads();
    }
    if (threadIdx.x == 0) g_partials[blockIdx.x] = sm[0];
}

__global__ void hist_kernel(const int* __restrict__ dst, int E) {
    int i = blockIdx.x * blockDim.x + threadIdx.x;
    if (i < E) atomicAdd(&g_cnt[dst[i]], 1);
}

// ---------------- CSR build: multi-block scan chain (R5-proven, ~5us each) ----------------
__global__ void scan1_kernel(int N) {
    __shared__ int sm[256];
    int node = blockIdx.x * 256 + threadIdx.x;
    int c = (node < N) ? g_cnt[node] : 0;
    sm[threadIdx.x] = c;
    __syncthreads();
    for (int o = 1; o < 256; o <<= 1) {
        int v = (threadIdx.x >= o) ? sm[threadIdx.x - o] : 0;
        __syncthreads();
        sm[threadIdx.x] += v;
        __syncthreads();
    }
    if (node <= N) g_rowptr[node] = sm[threadIdx.x] - c;
    if (threadIdx.x == 255) g_bsum[blockIdx.x] = sm[255];
}

__global__ void scan2_kernel(int nb) {
    __shared__ int sm[256];
    int c = (threadIdx.x < nb) ? g_bsum[threadIdx.x] : 0;
    sm[threadIdx.x] = c;
    __syncthreads();
    for (int o = 1; o < 256; o <<= 1) {
        int v = (threadIdx.x >= o) ? sm[threadIdx.x - o] : 0;
        __syncthreads();
        sm[threadIdx.x] += v;
        __syncthreads();
    }
    g_bsum[threadIdx.x] = sm[threadIdx.x] - c;
}

// scan3: rowptr/off finalize + dinv + norm2 finalize (block 0)
__global__ void scan3_kernel(int N, int E) {
    if (blockIdx.x == 0) {
        __shared__ float fm[256];
        fm[threadIdx.x] = g_partials[threadIdx.x] + g_partials[threadIdx.x + 256];
        __syncthreads();
        for (int o = 128; o > 0; o >>= 1) {
            if (threadIdx.x < o) fm[threadIdx.x] += fm[threadIdx.x + o];
            __syncthreads();
        }
        if (threadIdx.x == 0) g_norm2 = fm[0];
    }
    int node = blockIdx.x * 256 + threadIdx.x;
    if (node < N) {
        int r = g_rowptr[node] + g_bsum[blockIdx.x];
        g_rowptr[node] = r;
        g_off[node] = r;
        g_dinv[node] = rsqrtf((float)(g_cnt[node] + 1));  // +1 self-loop
    } else if (node == N) {
        g_rowptr[N] = E;
    }
}

__global__ void fill_kernel(const int* __restrict__ src, const int* __restrict__ dst, int E) {
    int i = blockIdx.x * blockDim.x + threadIdx.x;
    if (i < E) {
        int pos = atomicAdd(&g_off[dst[i]], 1);
        g_adj[pos] = src[i];
    }
}

// ---------------- GEMM: hs = fp16( (out_dinv? dinv[row]:1) * ((X + bin) @ W) ) ----------------
// hs row stride = 128 halves.  [proven 128row/256thr config]
__global__ void __launch_bounds__(256)
gemm_kernel(const float* __restrict__ X, const float* __restrict__ W,
            const float* __restrict__ bin, int out_dinv,
            __half* __restrict__ hs, int N) {
    extern __shared__ float smem[];
    float* sW = smem;          // 10000 floats
    float* sX = smem + 10000;  // 128*100 = 12800 floats
    int tid = threadIdx.x;
    int row0 = blockIdx.x * 128;

    for (int i = tid; i < 2500; i += 256)
        ((float4*)sW)[i] = __ldg((const float4*)W + i);
    for (int i = tid; i < 3200; i += 256) {
        int r = i / 25, c = i - r * 25;
        int gr = row0 + r;
        float4 v = make_float4(0.f, 0.f, 0.f, 0.f);
        if (gr < N) {
            v = __ldg((const float4*)(X + (size_t)gr * 100) + c);
            if (bin) {
                float4 b = __ldg((const float4*)bin + c);
                v.x += b.x; v.y += b.y; v.z += b.z; v.w += b.w;
            }
        }
        *((float4*)(sX + r * 100) + c) = v;
    }
    __syncthreads();

    int tx = tid & 3, ty = tid >> 2;
    float a0[25], a1[25];
#pragma unroll
    for (int c = 0; c < 25; c++) { a0[c] = 0.f; a1[c] = 0.f; }
    const float* x0p = sX + ty * 100;
    const float* x1p = sX + (ty + 64) * 100;
    const float* wcol = sW + tx * 25;
#pragma unroll 2
    for (int k = 0; k < 100; k++) {
        float x0 = x0p[k];
        float x1 = x1p[k];
        const float* wr = wcol + k * 100;
#pragma unroll
        for (int c = 0; c < 25; c++) {
            float w = wr[c];
            a0[c] += x0 * w;
            a1[c] += x1 * w;
        }
    }

    int gr0 = row0 + ty;
    int gr1 = row0 + ty + 64;
    if (gr0 < N) {
        float s = out_dinv ? g_dinv[gr0] : 1.0f;
        __half* p = hs + (size_t)gr0 * 128 + tx * 25;
#pragma unroll
        for (int c = 0; c < 25; c++) p[c] = __float2half_rn(a0[c] * s);
    }
    if (gr1 < N) {
        float s = out_dinv ? g_dinv[gr1] : 1.0f;
        __half* p = hs + (size_t)gr1 * 128 + tx * 25;
#pragma unroll
        for (int c = 0; c < 25; c++) p[c] = __float2half_rn(a1[c] * s);
    }
}

// ---------------- CSR agg (warp per node, lanes 0..24 own 4 cols) ----------------
// PRESCALED=0 (layer0): acc = dinv_i*rsqrt(norm2) * (dinv_i*hs_i + sum_j dinv_j*hs_j)
// PRESCALED=1 (layer1): acc = hs_i + sum_j hs_j      (hs already dinv-scaled)
template<int PRESCALED>
__global__ void __launch_bounds__(256)
agg_kernel(const __half* __restrict__ hs, float* __restrict__ acc,
           const int* __restrict__ rowptr, const int* __restrict__ adj, int N) {
    int node = (blockIdx.x * 256 + threadIdx.x) >> 5;
    int lane = threadIdx.x & 31;
    if (node >= N) return;
    bool act = lane < 25;
    float di = g_dinv[node];

    float4 sum = make_float4(0.f, 0.f, 0.f, 0.f);
    if (act) {
        uint2 raw = __ldg((const uint2*)(hs + (size_t)node * 128) + lane);
        float2 f0 = __half22float2(*(const __half2*)&raw.x);
        float2 f1 = __half22float2(*(const __half2*)&raw.y);
        float sf = PRESCALED ? 1.0f : di;
        sum.x = sf * f0.x; sum.y = sf * f0.y;
        sum.z = sf * f1.x; sum.w = sf * f1.y;
    }

    int beg = rowptr[node];
    int end = rowptr[node + 1];
    for (int base = beg; base < end; base += 32) {
        int idx = base + lane;
        int my = 0; float md = 0.f;
        if (idx < end) {
            my = __ldg(adj + idx);
            if (!PRESCALED) md = g_dinv[my];
        }
        int cnt = min(32, end - base);
#pragma unroll 4
        for (int j = 0; j < cnt; j++) {
            int s = __shfl_sync(0xffffffffu, my, j);
            float d = PRESCALED ? 1.0f : __shfl_sync(0xffffffffu, md, j);
            if (act) {
                uint2 raw = __ldg((const uint2*)(hs + (size_t)s * 128) + lane);
                float2 f0 = __half22float2(*(const __half2*)&raw.x);
                float2 f1 = __half22float2(*(const __half2*)&raw.y);
                if (PRESCALED) {
                    sum.x += f0.x; sum.y += f0.y; sum.z += f1.x; sum.w += f1.y;
                } else {
                    sum.x += d * f0.x; sum.y += d * f0.y;
                    sum.z += d * f1.x; sum.w += d * f1.y;
                }
            }
        }
    }
    if (act) {
        if (!PRESCALED) {
            float os = di * rsqrtf(g_norm2);
            sum.x *= os; sum.y *= os; sum.z *= os; sum.w *= os;
        }
        *((float4*)(acc + (size_t)node * 100) + lane) = sum;
    }
}

// ---------------- MLP head: out[i] = relu((dinv_i*acc + cb1) @ W0 + b0) @ W1 + b1 ----------------
__global__ void head_kernel(const float* __restrict__ acc, const float* __restrict__ bconv,
                            const float* __restrict__ W0, const float* __restrict__ b0,
                            const float* __restrict__ W1, const float* __restrict__ b1,
                            float* __restrict__ out, int N) {
    __shared__ float xs[64 * 101];
    __shared__ float w0s[1000];
    __shared__ float w1s[10];
    __shared__ float b0s[10];
    __shared__ float bcs[100];
    int tid = threadIdx.x;
    int base = blockIdx.x * 64;

    for (int i = tid; i < 1000; i += 128) w0s[i] = W0[i];
    if (tid < 10) { w1s[tid] = W1[tid]; b0s[tid] = b0[tid]; }
    if (tid < 100) bcs[tid] = bconv[tid];
    __syncthreads();

    for (int i = tid; i < 6400; i += 128) {
        int r = i / 100, k = i - r * 100;
        int g = base + r;
        xs[r * 101 + k] = (g < N) ? (g_dinv[g] * acc[(size_t)g * 100 + k] + bcs[k]) : 0.f;
    }
    __syncthreads();

    if (tid < 64) {
        int g = base + tid;
        if (g < N) {
            float y[10];
#pragma unroll
            for (int j = 0; j < 10; j++) y[j] = b0s[j];
            const float* xr = xs + tid * 101;
            for (int k = 0; k < 100; k++) {
                float xv = xr[k];
#pragma unroll
                for (int j = 0; j < 10; j++) y[j] += xv * w0s[k * 10 + j];
            }
            float o = b1[0];
#pragma unroll
            for (int j = 0; j < 10; j++) o += fmaxf(y[j], 0.f) * w1s[j];
            out[g] = o;
        }
    }
}

extern "C" void kernel_launch(void* const* d_in, const int* in_sizes, int n_in,
                              void* d_out, int out_size) {
    const float* x   = (const float*)d_in[0];
    const int*   ei  = (const int*)d_in[1];
    const float* W0  = (const float*)d_in[2];
    const float* cb0 = (const float*)d_in[3];
    const float* W1  = (const float*)d_in[4];
    const float* cb1 = (const float*)d_in[5];
    const float* lW0 = (const float*)d_in[6];
    const float* lb0 = (const float*)d_in[7];
    const float* lW1 = (const float*)d_in[8];
    const float* lb1 = (const float*)d_in[9];
    float* out = (float*)d_out;

    int N = in_sizes[0] / 100;
    int E = in_sizes[1] / 2;
    const int* src = ei;
    const int* dst = ei + E;

    size_t gemm_smem = (10000 + 12800) * sizeof(float);  // 91.2 KB -> 2 blocks/SM
    cudaFuncSetAttribute(gemm_kernel,
                         cudaFuncAttributeMaxDynamicSharedMemorySize, (int)gemm_smem);

    __half* hs;
    float* acc;
    int *rowptr, *adj;
    cudaGetSymbolAddress((void**)&hs, g_hs);
    cudaGetSymbolAddress((void**)&acc, g_acc);
    cudaGetSymbolAddress((void**)&rowptr, g_rowptr);
    cudaGetSymbolAddress((void**)&adj, g_adj);

    cudaStream_t s2;
    cudaStreamCreateWithFlags(&s2, cudaStreamNonBlocking);
    cudaEvent_t ev0, ev1;
    cudaEventCreateWithFlags(&ev0, cudaEventDisableTiming);
    cudaEventCreateWithFlags(&ev1, cudaEventDisableTiming);

    cudaEventRecord(ev0, 0);
    cudaStreamWaitEvent(s2, ev0, 0);

    // branch B (default): gemm0 = raw x @ W0, no dependencies on branch A
    int gblocks = (N + 127) / 128;
    gemm_kernel<<<gblocks, 256, gemm_smem>>>(x, W0, nullptr, 0, hs, N);

    // branch A (s2): norm + degrees + CSR, fully overlapped with gemm0
    long n_elem = (long)N * 100;
    prep_kernel<<<512, 256, 0, s2>>>(x, n_elem, N);
    hist_kernel<<<(E + 255) / 256, 256, 0, s2>>>(dst, E);
    int nscan = (N + 256) / 256;
    scan1_kernel<<<nscan, 256, 0, s2>>>(N);
    scan2_kernel<<<1, 256, 0, s2>>>(nscan);
    scan3_kernel<<<nscan, 256, 0, s2>>>(N, E);
    fill_kernel<<<(E + 255) / 256, 256, 0, s2>>>(src, dst, E);
    cudaEventRecord(ev1, s2);

    cudaStreamWaitEvent(0, ev1, 0);  // join

    int ablocks = (N + 7) / 8;  // warp per node
    agg_kernel<0><<<ablocks, 256>>>(hs, acc, rowptr, adj, N);
    gemm_kernel<<<gblocks, 256, gemm_smem>>>(acc, W1, cb0, 1, hs, N);
    agg_kernel<1><<<ablocks, 256>>>(hs, acc, rowptr, adj, N);
    head_kernel<<<(N + 63) / 64, 128>>>(acc, cb1, lW0, lb0, lW1, lb1, out, N);
}

// round 8
// speedup vs baseline: 1.4635x; 1.0410x over previous
#include <cuda_runtime.h>
#include <cuda_fp16.h>
#include <math.h>

// ---------------- scratch (no allocation allowed) ----------------
__device__ __half g_hs[6400000];   // 50000 x 128 halves (256B-aligned rows)
__device__ float  g_acc[5000000];  // 50000 x 100 fp32 (reused across layers)
__device__ float  g_dinv[50048];
__device__ int    g_cnt[50048];    // statically zero; re-zeroed by scan3 each call
__device__ int    g_rowptr[50049];
__device__ int    g_off[50049];
__device__ int    g_adj[800064];
__device__ int    g_bsum[256];
__device__ float  g_partials[512];
__device__ float  g_norm2;

// ---------------- fused prep: ||x||^2 partials + degree histogram ----------------
// g_cnt is guaranteed zero on entry (static init on first call; scan3 re-zeroes after).
__global__ void prephist_kernel(const float* __restrict__ x, long n,
                                const int* __restrict__ dst, int E) {
    int gs = gridDim.x * blockDim.x;
    int g0 = blockIdx.x * blockDim.x + threadIdx.x;
    for (int i = g0; i < E; i += gs) atomicAdd(&g_cnt[dst[i]], 1);
    float s = 0.f;
    for (long i = g0; i < n; i += gs) {
        float v = x[i];
        s += v * v;
    }
    __shared__ float sm[256];
    sm[threadIdx.x] = s;
    __syncthreads();
    for (int o = 128; o > 0; o >>= 1) {
        if (threadIdx.x < o) sm[threadIdx.x] += sm[threadIdx.x + o];
        __syncthreads();
    }
    if (threadIdx.x == 0) g_partials[blockIdx.x] = sm[0];
}

// dinv from degrees + finalize norm2 (block 0)
__global__ void dinv_norm_kernel(int N) {
    if (blockIdx.x == 0) {
        __shared__ float fm[256];
        fm[threadIdx.x] = g_partials[threadIdx.x] + g_partials[threadIdx.x + 256];
        __syncthreads();
        for (int o = 128; o > 0; o >>= 1) {
            if (threadIdx.x < o) fm[threadIdx.x] += fm[threadIdx.x + o];
            __syncthreads();
        }
        if (threadIdx.x == 0) g_norm2 = fm[0];
    }
    int i = blockIdx.x * 256 + threadIdx.x;
    if (i < N) g_dinv[i] = rsqrtf((float)(g_cnt[i] + 1));  // +1 self-loop
}

// ---------------- CSR build: multi-block scan chain (proven ~5us each) ----------------
__global__ void scan1_kernel(int N) {
    __shared__ int sm[256];
    int node = blockIdx.x * 256 + threadIdx.x;
    int c = (node < N) ? g_cnt[node] : 0;
    sm[threadIdx.x] = c;
    __syncthreads();
    for (int o = 1; o < 256; o <<= 1) {
        int v = (threadIdx.x >= o) ? sm[threadIdx.x - o] : 0;
        __syncthreads();
        sm[threadIdx.x] += v;
        __syncthreads();
    }
    if (node <= N) g_rowptr[node] = sm[threadIdx.x] - c;
    if (threadIdx.x == 255) g_bsum[blockIdx.x] = sm[255];
}

__global__ void scan2_kernel(int nb) {
    __shared__ int sm[256];
    int c = (threadIdx.x < nb) ? g_bsum[threadIdx.x] : 0;
    sm[threadIdx.x] = c;
    __syncthreads();
    for (int o = 1; o < 256; o <<= 1) {
        int v = (threadIdx.x >= o) ? sm[threadIdx.x - o] : 0;
        __syncthreads();
        sm[threadIdx.x] += v;
        __syncthreads();
    }
    g_bsum[threadIdx.x] = sm[threadIdx.x] - c;
}

// finalize rowptr/off; re-zero g_cnt for the next graph replay
__global__ void scan3_kernel(int N, int E) {
    int node = blockIdx.x * 256 + threadIdx.x;
    if (node < N) {
        int r = g_rowptr[node] + g_bsum[blockIdx.x];
        g_rowptr[node] = r;
        g_off[node] = r;
        g_cnt[node] = 0;  // reset for next call (deterministic)
    } else if (node == N) {
        g_rowptr[N] = E;
    }
}

__global__ void fill_kernel(const int* __restrict__ src, const int* __restrict__ dst, int E) {
    int i = blockIdx.x * blockDim.x + threadIdx.x;
    if (i < E) {
        int pos = atomicAdd(&g_off[dst[i]], 1);
        g_adj[pos] = src[i];
    }
}

// ---------------- GEMM: hs = fp16( dinv[row] * ((inscale(row)*X + bin) @ W) ) ----------------
// use_inscale: v = (dinv[row]*rsqrt(norm2))*X + bin  (layer 1 input transform)
// hs row stride = 128 halves.  [R5-proven 128row/256thr config]
__global__ void __launch_bounds__(256)
gemm_kernel(const float* __restrict__ X, const float* __restrict__ W,
            const float* __restrict__ bin, int use_inscale,
            __half* __restrict__ hs, int N) {
    extern __shared__ float smem[];
    float* sW = smem;          // 10000 floats
    float* sX = smem + 10000;  // 128*100 = 12800 floats
    int tid = threadIdx.x;
    int row0 = blockIdx.x * 128;

    float nminv = use_inscale ? rsqrtf(g_norm2) : 1.0f;

    for (int i = tid; i < 2500; i += 256)
        ((float4*)sW)[i] = __ldg((const float4*)W + i);
    for (int i = tid; i < 3200; i += 256) {
        int r = i / 25, c = i - r * 25;
        int gr = row0 + r;
        float4 v = make_float4(0.f, 0.f, 0.f, 0.f);
        if (gr < N) {
            v = __ldg((const float4*)(X + (size_t)gr * 100) + c);
            if (use_inscale) {
                float s = g_dinv[gr] * nminv;
                float4 b = __ldg((const float4*)bin + c);
                v.x = v.x * s + b.x; v.y = v.y * s + b.y;
                v.z = v.z * s + b.z; v.w = v.w * s + b.w;
            }
        }
        *((float4*)(sX + r * 100) + c) = v;
    }
    __syncthreads();

    int tx = tid & 3, ty = tid >> 2;
    float a0[25], a1[25];
#pragma unroll
    for (int c = 0; c < 25; c++) { a0[c] = 0.f; a1[c] = 0.f; }
    const float* x0p = sX + ty * 100;
    const float* x1p = sX + (ty + 64) * 100;
    const float* wcol = sW + tx * 25;
#pragma unroll 2
    for (int k = 0; k < 100; k++) {
        float x0 = x0p[k];
        float x1 = x1p[k];
        const float* wr = wcol + k * 100;
#pragma unroll
        for (int c = 0; c < 25; c++) {
            float w = wr[c];
            a0[c] += x0 * w;
            a1[c] += x1 * w;
        }
    }

    int gr0 = row0 + ty;
    int gr1 = row0 + ty + 64;
    if (gr0 < N) {
        float s = g_dinv[gr0];
        __half* p = hs + (size_t)gr0 * 128 + tx * 25;
#pragma unroll
        for (int c = 0; c < 25; c++) p[c] = __float2half_rn(a0[c] * s);
    }
    if (gr1 < N) {
        float s = g_dinv[gr1];
        __half* p = hs + (size_t)gr1 * 128 + tx * 25;
#pragma unroll
        for (int c = 0; c < 25; c++) p[c] = __float2half_rn(a1[c] * s);
    }
}

// ---------------- CSR agg: acc[i] = hs[i] + sum_{j in adj[i]} hs[j]  (fp32 accum) ----------------
// one warp per node; lanes 0..24 own 4 cols (uint2 = 4 halves); unroll 8 for MLP
__global__ void __launch_bounds__(256)
agg_kernel(const __half* __restrict__ hs, float* __restrict__ acc,
           const int* __restrict__ rowptr, const int* __restrict__ adj, int N) {
    int node = (blockIdx.x * 256 + threadIdx.x) >> 5;
    int lane = threadIdx.x & 31;
    if (node >= N) return;
    bool act = lane < 25;

    float4 sum = make_float4(0.f, 0.f, 0.f, 0.f);
    if (act) {
        uint2 raw = __ldg((const uint2*)(hs + (size_t)node * 128) + lane);
        float2 f0 = __half22float2(*(const __half2*)&raw.x);
        float2 f1 = __half22float2(*(const __half2*)&raw.y);
        sum.x = f0.x; sum.y = f0.y; sum.z = f1.x; sum.w = f1.y;
    }

    int beg = rowptr[node];
    int end = rowptr[node + 1];
    for (int base = beg; base < end; base += 32) {
        int idx = base + lane;
        int my = (idx < end) ? __ldg(adj + idx) : 0;
        int cnt = min(32, end - base);
#pragma unroll 8
        for (int j = 0; j < cnt; j++) {
            int s = __shfl_sync(0xffffffffu, my, j);
            if (act) {
                uint2 raw = __ldg((const uint2*)(hs + (size_t)s * 128) + lane);
                float2 f0 = __half22float2(*(const __half2*)&raw.x);
                float2 f1 = __half22float2(*(const __half2*)&raw.y);
                sum.x += f0.x; sum.y += f0.y; sum.z += f1.x; sum.w += f1.y;
            }
        }
    }
    if (act)
        *((float4*)(acc + (size_t)node * 100) + lane) = sum;
}

// ---------------- MLP head: out[i] = relu((dinv_i*acc + cb1) @ W0 + b0) @ W1 + b1 ----------------
__global__ void head_kernel(const float* __restrict__ acc, const float* __restrict__ bconv,
                            const float* __restrict__ W0, const float* __restrict__ b0,
                            const float* __restrict__ W1, const float* __restrict__ b1,
                            float* __restrict__ out, int N) {
    __shared__ float xs[64 * 101];
    __shared__ float w0s[1000];
    __shared__ float w1s[10];
    __shared__ float b0s[10];
    __shared__ float bcs[100];
    int tid = threadIdx.x;
    int base = blockIdx.x * 64;

    for (int i = tid; i < 1000; i += 128) w0s[i] = W0[i];
    if (tid < 10) { w1s[tid] = W1[tid]; b0s[tid] = b0[tid]; }
    if (tid < 100) bcs[tid] = bconv[tid];
    __syncthreads();

    for (int i = tid; i < 6400; i += 128) {
        int r = i / 100, k = i - r * 100;
        int g = base + r;
        xs[r * 101 + k] = (g < N) ? (g_dinv[g] * acc[(size_t)g * 100 + k] + bcs[k]) : 0.f;
    }
    __syncthreads();

    if (tid < 64) {
        int g = base + tid;
        if (g < N) {
            float y[10];
#pragma unroll
            for (int j = 0; j < 10; j++) y[j] = b0s[j];
            const float* xr = xs + tid * 101;
            for (int k = 0; k < 100; k++) {
                float xv = xr[k];
#pragma unroll
                for (int j = 0; j < 10; j++) y[j] += xv * w0s[k * 10 + j];
            }
            float o = b1[0];
#pragma unroll
            for (int j = 0; j < 10; j++) o += fmaxf(y[j], 0.f) * w1s[j];
            out[g] = o;
        }
    }
}

extern "C" void kernel_launch(void* const* d_in, const int* in_sizes, int n_in,
                              void* d_out, int out_size) {
    const float* x   = (const float*)d_in[0];
    const int*   ei  = (const int*)d_in[1];
    const float* W0  = (const float*)d_in[2];
    const float* cb0 = (const float*)d_in[3];
    const float* W1  = (const float*)d_in[4];
    const float* cb1 = (const float*)d_in[5];
    const float* lW0 = (const float*)d_in[6];
    const float* lb0 = (const float*)d_in[7];
    const float* lW1 = (const float*)d_in[8];
    const float* lb1 = (const float*)d_in[9];
    float* out = (float*)d_out;

    int N = in_sizes[0] / 100;
    int E = in_sizes[1] / 2;
    const int* src = ei;
    const int* dst = ei + E;

    size_t gemm_smem = (10000 + 12800) * sizeof(float);  // 91.2 KB -> 2 blocks/SM
    cudaFuncSetAttribute(gemm_kernel,
                         cudaFuncAttributeMaxDynamicSharedMemorySize, (int)gemm_smem);

    __half* hs;
    float* acc;
    int *rowptr, *adj;
    cudaGetSymbolAddress((void**)&hs, g_hs);
    cudaGetSymbolAddress((void**)&acc, g_acc);
    cudaGetSymbolAddress((void**)&rowptr, g_rowptr);
    cudaGetSymbolAddress((void**)&adj, g_adj);

    // phase 0 (serial): fused degrees+norm partials, then dinv (gemm0 epilogue needs dinv)
    long n_elem = (long)N * 100;
    prephist_kernel<<<512, 256>>>(x, n_elem, dst, E);
    dinv_norm_kernel<<<(N + 255) / 256, 256>>>(N);

    // fork: branch A (CSR scan+fill) on s2  ||  branch B (gemm0) on default
    cudaStream_t s2;
    cudaStreamCreateWithFlags(&s2, cudaStreamNonBlocking);
    cudaEvent_t ev0, ev1;
    cudaEventCreateWithFlags(&ev0, cudaEventDisableTiming);
    cudaEventCreateWithFlags(&ev1, cudaEventDisableTiming);

    cudaEventRecord(ev0, 0);
    cudaStreamWaitEvent(s2, ev0, 0);

    int nscan = (N + 256) / 256;
    scan1_kernel<<<nscan, 256, 0, s2>>>(N);

    // gemm0 issued 4th -> profiled next round
    int gblocks = (N + 127) / 128;
    gemm_kernel<<<gblocks, 256, gemm_smem>>>(x, W0, nullptr, 0, hs, N);

    scan2_kernel<<<1, 256, 0, s2>>>(nscan);
    scan3_kernel<<<nscan, 256, 0, s2>>>(N, E);
    fill_kernel<<<(E + 255) / 256, 256, 0, s2>>>(src, dst, E);
    cudaEventRecord(ev1, s2);

    cudaStreamWaitEvent(0, ev1, 0);  // join

    int ablocks = (N + 7) / 8;  // warp per node
    agg_kernel<<<ablocks, 256>>>(hs, acc, rowptr, adj, N);
    gemm_kernel<<<gblocks, 256, gemm_smem>>>(acc, W1, cb0, 1, hs, N);
    agg_kernel<<<ablocks, 256>>>(hs, acc, rowptr, adj, N);
    head_kernel<<<(N + 63) / 64, 128>>>(acc, cb1, lW0, lb0, lW1, lb1, out, N);
}

// round 9
// speedup vs baseline: 1.8966x; 1.2960x over previous
#include <cuda_runtime.h>
#include <cuda_fp16.h>
#include <math.h>
#include <stdint.h>

// ---------------- scratch (no allocation allowed) ----------------
__device__ __half g_hs[6400000];   // 50000 x 128 halves (256B-aligned rows)
__device__ float  g_acc[5000000];  // 50000 x 100 fp32 (reused across layers)
__device__ float  g_dinv[50048];
__device__ int    g_cnt[50048];    // statically zero; re-zeroed by scan3 each call
__device__ int    g_rowptr[50049];
__device__ int    g_off[50049];
__device__ int    g_adj[800064];
__device__ int    g_bsum[256];
__device__ float  g_partials[512];
__device__ float  g_norm2;

// ---------------- fused prep: ||x||^2 partials + degree histogram ----------------
__global__ void prephist_kernel(const float* __restrict__ x, long n,
                                const int* __restrict__ dst, int E) {
    int gs = gridDim.x * blockDim.x;
    int g0 = blockIdx.x * blockDim.x + threadIdx.x;
    for (int i = g0; i < E; i += gs) atomicAdd(&g_cnt[dst[i]], 1);
    float s = 0.f;
    for (long i = g0; i < n; i += gs) {
        float v = x[i];
        s += v * v;
    }
    __shared__ float sm[256];
    sm[threadIdx.x] = s;
    __syncthreads();
    for (int o = 128; o > 0; o >>= 1) {
        if (threadIdx.x < o) sm[threadIdx.x] += sm[threadIdx.x + o];
        __syncthreads();
    }
    if (threadIdx.x == 0) g_partials[blockIdx.x] = sm[0];
}

__global__ void dinv_norm_kernel(int N) {
    if (blockIdx.x == 0) {
        __shared__ float fm[256];
        fm[threadIdx.x] = g_partials[threadIdx.x] + g_partials[threadIdx.x + 256];
        __syncthreads();
        for (int o = 128; o > 0; o >>= 1) {
            if (threadIdx.x < o) fm[threadIdx.x] += fm[threadIdx.x + o];
            __syncthreads();
        }
        if (threadIdx.x == 0) g_norm2 = fm[0];
    }
    int i = blockIdx.x * 256 + threadIdx.x;
    if (i < N) g_dinv[i] = rsqrtf((float)(g_cnt[i] + 1));
}

// ---------------- CSR build: multi-block scan chain ----------------
__global__ void scan1_kernel(int N) {
    __shared__ int sm[256];
    int node = blockIdx.x * 256 + threadIdx.x;
    int c = (node < N) ? g_cnt[node] : 0;
    sm[threadIdx.x] = c;
    __syncthreads();
    for (int o = 1; o < 256; o <<= 1) {
        int v = (threadIdx.x >= o) ? sm[threadIdx.x - o] : 0;
        __syncthreads();
        sm[threadIdx.x] += v;
        __syncthreads();
    }
    if (node <= N) g_rowptr[node] = sm[threadIdx.x] - c;
    if (threadIdx.x == 255) g_bsum[blockIdx.x] = sm[255];
}

__global__ void scan2_kernel(int nb) {
    __shared__ int sm[256];
    int c = (threadIdx.x < nb) ? g_bsum[threadIdx.x] : 0;
    sm[threadIdx.x] = c;
    __syncthreads();
    for (int o = 1; o < 256; o <<= 1) {
        int v = (threadIdx.x >= o) ? sm[threadIdx.x - o] : 0;
        __syncthreads();
        sm[threadIdx.x] += v;
        __syncthreads();
    }
    g_bsum[threadIdx.x] = sm[threadIdx.x] - c;
}

__global__ void scan3_kernel(int N, int E) {
    int node = blockIdx.x * 256 + threadIdx.x;
    if (node < N) {
        int r = g_rowptr[node] + g_bsum[blockIdx.x];
        g_rowptr[node] = r;
        g_off[node] = r;
        g_cnt[node] = 0;  // reset for next graph replay
    } else if (node == N) {
        g_rowptr[N] = E;
    }
}

__global__ void fill_kernel(const int* __restrict__ src, const int* __restrict__ dst, int E) {
    int i = blockIdx.x * blockDim.x + threadIdx.x;
    if (i < E) {
        int pos = atomicAdd(&g_off[dst[i]], 1);
        g_adj[pos] = src[i];
    }
}

// ---------------- tf32 tensor-core GEMM ----------------
// hs = fp16( dinv[row] * ((inscale(row)*X + bin) @ W) ),  hs row stride 128
// block: 256 thr = 8 warps, 128 rows (16/warp). K,N padded 100->104.
__device__ __forceinline__ uint32_t f2tf32(float v) {
    uint32_t t;
    asm("cvt.rna.tf32.f32 %0, %1;" : "=r"(t) : "f"(v));
    return t;
}

__global__ void __launch_bounds__(256)
gemm_mma_kernel(const float* __restrict__ X, const float* __restrict__ W,
                const float* __restrict__ bin, int use_inscale,
                __half* __restrict__ hs, int N) {
    extern __shared__ uint32_t smem_u[];
    uint32_t* sX = smem_u;            // 128 x 104 tf32
    uint32_t* sW = smem_u + 128 * 104; // 104 x 104 tf32 (k-major: sW[k*104+n])
    int tid = threadIdx.x;
    int row0 = blockIdx.x * 128;

    float nminv = use_inscale ? rsqrtf(g_norm2) : 1.0f;

    // stage W (pad k,n to 104 with zeros)
    for (int i = tid; i < 104 * 104; i += 256) {
        int k = i / 104, n = i - k * 104;
        float v = (k < 100 && n < 100) ? __ldg(W + k * 100 + n) : 0.f;
        sW[i] = f2tf32(v);
    }
    // stage X tile (pad cols to 104)
    for (int i = tid; i < 128 * 104; i += 256) {
        int r = i / 104, c = i - r * 104;
        int gr = row0 + r;
        float v = 0.f;
        if (gr < N && c < 100) {
            v = __ldg(X + (size_t)gr * 100 + c);
            if (use_inscale) v = v * (g_dinv[gr] * nminv) + __ldg(bin + c);
        }
        sX[i] = f2tf32(v);
    }
    __syncthreads();

    int warp = tid >> 5, lane = tid & 31;
    int grp = lane >> 2, tig = lane & 3;
    const uint32_t* xw = sX + (warp * 16) * 104;  // this warp's 16 rows

    float acc[13][4];
#pragma unroll
    for (int nt = 0; nt < 13; nt++)
#pragma unroll
        for (int i = 0; i < 4; i++) acc[nt][i] = 0.f;

    for (int kc = 0; kc < 13; kc++) {
        int k0 = kc * 8;
        uint32_t a0 = xw[grp * 104 + k0 + tig];
        uint32_t a1 = xw[(grp + 8) * 104 + k0 + tig];
        uint32_t a2 = xw[grp * 104 + k0 + tig + 4];
        uint32_t a3 = xw[(grp + 8) * 104 + k0 + tig + 4];
        const uint32_t* wr0 = sW + (k0 + tig) * 104 + grp;
        const uint32_t* wr1 = sW + (k0 + tig + 4) * 104 + grp;
#pragma unroll
        for (int nt = 0; nt < 13; nt++) {
            uint32_t b0 = wr0[nt * 8];
            uint32_t b1 = wr1[nt * 8];
            asm volatile(
                "mma.sync.aligned.m16n8k8.row.col.f32.tf32.tf32.f32 "
                "{%0,%1,%2,%3}, {%4,%5,%6,%7}, {%8,%9}, {%0,%1,%2,%3};"
                : "+f"(acc[nt][0]), "+f"(acc[nt][1]), "+f"(acc[nt][2]), "+f"(acc[nt][3])
                : "r"(a0), "r"(a1), "r"(a2), "r"(a3), "r"(b0), "r"(b1));
        }
    }

    // epilogue: rows grp and grp+8; cols nt*8 + 2*tig (+1)
    int gr0 = row0 + warp * 16 + grp;
    int gr1 = gr0 + 8;
    float s0 = (gr0 < N) ? g_dinv[gr0] : 0.f;
    float s1 = (gr1 < N) ? g_dinv[gr1] : 0.f;
#pragma unroll
    for (int nt = 0; nt < 13; nt++) {
        int col = nt * 8 + 2 * tig;
        if (gr0 < N) {
            __half2 h = __floats2half2_rn(acc[nt][0] * s0, acc[nt][1] * s0);
            *(__half2*)(hs + (size_t)gr0 * 128 + col) = h;
        }
        if (gr1 < N) {
            __half2 h = __floats2half2_rn(acc[nt][2] * s1, acc[nt][3] * s1);
            *(__half2*)(hs + (size_t)gr1 * 128 + col) = h;
        }
    }
}

// ---------------- CSR agg: acc[i] = hs[i] + sum_{j in adj[i]} hs[j]  (fp32 accum) ----------------
__global__ void __launch_bounds__(256)
agg_kernel(const __half* __restrict__ hs, float* __restrict__ acc,
           const int* __restrict__ rowptr, const int* __restrict__ adj, int N) {
    int node = (blockIdx.x * 256 + threadIdx.x) >> 5;
    int lane = threadIdx.x & 31;
    if (node >= N) return;
    bool act = lane < 25;

    float4 sum = make_float4(0.f, 0.f, 0.f, 0.f);
    if (act) {
        uint2 raw = __ldg((const uint2*)(hs + (size_t)node * 128) + lane);
        float2 f0 = __half22float2(*(const __half2*)&raw.x);
        float2 f1 = __half22float2(*(const __half2*)&raw.y);
        sum.x = f0.x; sum.y = f0.y; sum.z = f1.x; sum.w = f1.y;
    }

    int beg = rowptr[node];
    int end = rowptr[node + 1];
    for (int base = beg; base < end; base += 32) {
        int idx = base + lane;
        int my = (idx < end) ? __ldg(adj + idx) : 0;
        int cnt = min(32, end - base);
#pragma unroll 8
        for (int j = 0; j < cnt; j++) {
            int s = __shfl_sync(0xffffffffu, my, j);
            if (act) {
                uint2 raw = __ldg((const uint2*)(hs + (size_t)s * 128) + lane);
                float2 f0 = __half22float2(*(const __half2*)&raw.x);
                float2 f1 = __half22float2(*(const __half2*)&raw.y);
                sum.x += f0.x; sum.y += f0.y; sum.z += f1.x; sum.w += f1.y;
            }
        }
    }
    if (act)
        *((float4*)(acc + (size_t)node * 100) + lane) = sum;
}

// ---------------- MLP head ----------------
__global__ void head_kernel(const float* __restrict__ acc, const float* __restrict__ bconv,
                            const float* __restrict__ W0, const float* __restrict__ b0,
                            const float* __restrict__ W1, const float* __restrict__ b1,
                            float* __restrict__ out, int N) {
    __shared__ float xs[64 * 101];
    __shared__ float w0s[1000];
    __shared__ float w1s[10];
    __shared__ float b0s[10];
    __shared__ float bcs[100];
    int tid = threadIdx.x;
    int base = blockIdx.x * 64;

    for (int i = tid; i < 1000; i += 128) w0s[i] = W0[i];
    if (tid < 10) { w1s[tid] = W1[tid]; b0s[tid] = b0[tid]; }
    if (tid < 100) bcs[tid] = bconv[tid];
    __syncthreads();

    for (int i = tid; i < 6400; i += 128) {
        int r = i / 100, k = i - r * 100;
        int g = base + r;
        xs[r * 101 + k] = (g < N) ? (g_dinv[g] * acc[(size_t)g * 100 + k] + bcs[k]) : 0.f;
    }
    __syncthreads();

    if (tid < 64) {
        int g = base + tid;
        if (g < N) {
            float y[10];
#pragma unroll
            for (int j = 0; j < 10; j++) y[j] = b0s[j];
            const float* xr = xs + tid * 101;
            for (int k = 0; k < 100; k++) {
                float xv = xr[k];
#pragma unroll
                for (int j = 0; j < 10; j++) y[j] += xv * w0s[k * 10 + j];
            }
            float o = b1[0];
#pragma unroll
            for (int j = 0; j < 10; j++) o += fmaxf(y[j], 0.f) * w1s[j];
            out[g] = o;
        }
    }
}

extern "C" void kernel_launch(void* const* d_in, const int* in_sizes, int n_in,
                              void* d_out, int out_size) {
    const float* x   = (const float*)d_in[0];
    const int*   ei  = (const int*)d_in[1];
    const float* W0  = (const float*)d_in[2];
    const float* cb0 = (const float*)d_in[3];
    const float* W1  = (const float*)d_in[4];
    const float* cb1 = (const float*)d_in[5];
    const float* lW0 = (const float*)d_in[6];
    const float* lb0 = (const float*)d_in[7];
    const float* lW1 = (const float*)d_in[8];
    const float* lb1 = (const float*)d_in[9];
    float* out = (float*)d_out;

    int N = in_sizes[0] / 100;
    int E = in_sizes[1] / 2;
    const int* src = ei;
    const int* dst = ei + E;

    size_t gemm_smem = (128 * 104 + 104 * 104) * sizeof(uint32_t);  // 96.5 KB -> 2 blocks/SM
    cudaFuncSetAttribute(gemm_mma_kernel,
                         cudaFuncAttributeMaxDynamicSharedMemorySize, (int)gemm_smem);

    __half* hs;
    float* acc;
    int *rowptr, *adj;
    cudaGetSymbolAddress((void**)&hs, g_hs);
    cudaGetSymbolAddress((void**)&acc, g_acc);
    cudaGetSymbolAddress((void**)&rowptr, g_rowptr);
    cudaGetSymbolAddress((void**)&adj, g_adj);

    // phase 0 (serial): degrees + norm partials, then dinv
    long n_elem = (long)N * 100;
    prephist_kernel<<<512, 256>>>(x, n_elem, dst, E);
    dinv_norm_kernel<<<(N + 255) / 256, 256>>>(N);

    // fork: branch A (CSR scan+fill) on s2  ||  branch B (gemm0) on default
    cudaStream_t s2;
    cudaStreamCreateWithFlags(&s2, cudaStreamNonBlocking);
    cudaEvent_t ev0, ev1;
    cudaEventCreateWithFlags(&ev0, cudaEventDisableTiming);
    cudaEventCreateWithFlags(&ev1, cudaEventDisableTiming);

    cudaEventRecord(ev0, 0);
    cudaStreamWaitEvent(s2, ev0, 0);

    int nscan = (N + 256) / 256;
    scan1_kernel<<<nscan, 256, 0, s2>>>(N);

    int gblocks = (N + 127) / 128;
    gemm_mma_kernel<<<gblocks, 256, gemm_smem>>>(x, W0, nullptr, 0, hs, N);

    scan2_kernel<<<1, 256, 0, s2>>>(nscan);
    scan3_kernel<<<nscan, 256, 0, s2>>>(N, E);
    fill_kernel<<<(E + 255) / 256, 256, 0, s2>>>(src, dst, E);
    cudaEventRecord(ev1, s2);

    cudaStreamWaitEvent(0, ev1, 0);  // join

    int ablocks = (N + 7) / 8;
    agg_kernel<<<ablocks, 256>>>(hs, acc, rowptr, adj, N);
    gemm_mma_kernel<<<gblocks, 256, gemm_smem>>>(acc, W1, cb0, 1, hs, N);
    agg_kernel<<<ablocks, 256>>>(hs, acc, rowptr, adj, N);
    head_kernel<<<(N + 63) / 64, 128>>>(acc, cb1, lW0, lb0, lW1, lb1, out, N);
}

// round 10
// speedup vs baseline: 2.7070x; 1.4273x over previous
#include <cuda_runtime.h>
#include <cuda_fp16.h>
#include <math.h>
#include <stdint.h>

// ---------------- scratch (no allocation allowed) ----------------
__device__ __half g_hs[6400000];   // 50000 x 128 halves (256B-aligned rows)
__device__ float  g_acc[5000000];  // 50000 x 100 fp32 (reused across layers)
__device__ float  g_dinv[50048];
__device__ int    g_cnt[50048];    // statically zero; re-zeroed by scan3 each call
__device__ int    g_rowptr[50049];
__device__ int    g_off[50049];
__device__ int    g_adj[800064];
__device__ int    g_bsum[256];
__device__ float  g_partials[512];
__device__ float  g_norm2;

// ---------------- fused prep: ||x||^2 partials + degree histogram ----------------
__global__ void prephist_kernel(const float* __restrict__ x, long n,
                                const int* __restrict__ dst, int E) {
    int gs = gridDim.x * blockDim.x;
    int g0 = blockIdx.x * blockDim.x + threadIdx.x;
    for (int i = g0; i < E; i += gs) atomicAdd(&g_cnt[dst[i]], 1);
    float s = 0.f;
    for (long i = g0; i < n; i += gs) {
        float v = x[i];
        s += v * v;
    }
    __shared__ float sm[256];
    sm[threadIdx.x] = s;
    __syncthreads();
    for (int o = 128; o > 0; o >>= 1) {
        if (threadIdx.x < o) sm[threadIdx.x] += sm[threadIdx.x + o];
        __syncthreads();
    }
    if (threadIdx.x == 0) g_partials[blockIdx.x] = sm[0];
}

__global__ void dinv_norm_kernel(int N) {
    if (blockIdx.x == 0) {
        __shared__ float fm[256];
        fm[threadIdx.x] = g_partials[threadIdx.x] + g_partials[threadIdx.x + 256];
        __syncthreads();
        for (int o = 128; o > 0; o >>= 1) {
            if (threadIdx.x < o) fm[threadIdx.x] += fm[threadIdx.x + o];
            __syncthreads();
        }
        if (threadIdx.x == 0) g_norm2 = fm[0];
    }
    int i = blockIdx.x * 256 + threadIdx.x;
    if (i < N) g_dinv[i] = rsqrtf((float)(g_cnt[i] + 1));
}

// ---------------- CSR build: multi-block scan chain ----------------
__global__ void scan1_kernel(int N) {
    __shared__ int sm[256];
    int node = blockIdx.x * 256 + threadIdx.x;
    int c = (node < N) ? g_cnt[node] : 0;
    sm[threadIdx.x] = c;
    __syncthreads();
    for (int o = 1; o < 256; o <<= 1) {
        int v = (threadIdx.x >= o) ? sm[threadIdx.x - o] : 0;
        __syncthreads();
        sm[threadIdx.x] += v;
        __syncthreads();
    }
    if (node <= N) g_rowptr[node] = sm[threadIdx.x] - c;
    if (threadIdx.x == 255) g_bsum[blockIdx.x] = sm[255];
}

__global__ void scan2_kernel(int nb) {
    __shared__ int sm[256];
    int c = (threadIdx.x < nb) ? g_bsum[threadIdx.x] : 0;
    sm[threadIdx.x] = c;
    __syncthreads();
    for (int o = 1; o < 256; o <<= 1) {
        int v = (threadIdx.x >= o) ? sm[threadIdx.x - o] : 0;
        __syncthreads();
        sm[threadIdx.x] += v;
        __syncthreads();
    }
    g_bsum[threadIdx.x] = sm[threadIdx.x] - c;
}

__global__ void scan3_kernel(int N, int E) {
    int node = blockIdx.x * 256 + threadIdx.x;
    if (node < N) {
        int r = g_rowptr[node] + g_bsum[blockIdx.x];
        g_rowptr[node] = r;
        g_off[node] = r;
        g_cnt[node] = 0;  // reset for next graph replay
    } else if (node == N) {
        g_rowptr[N] = E;
    }
}

__global__ void fill_kernel(const int* __restrict__ src, const int* __restrict__ dst, int E) {
    int i = blockIdx.x * blockDim.x + threadIdx.x;
    if (i < E) {
        int pos = atomicAdd(&g_off[dst[i]], 1);
        g_adj[pos] = src[i];
    }
}

// ---------------- tf32 tensor-core GEMM (pure): hs = fp16(dinv[row] * (X @ W)) ----------------
__device__ __forceinline__ uint32_t f2tf32(float v) {
    uint32_t t;
    asm("cvt.rna.tf32.f32 %0, %1;" : "=r"(t) : "f"(v));
    return t;
}

__global__ void __launch_bounds__(256)
gemm_mma_kernel(const float* __restrict__ X, const float* __restrict__ W,
                __half* __restrict__ hs, int N) {
    extern __shared__ uint32_t smem_u[];
    uint32_t* sX = smem_u;             // 128 x 104 tf32
    uint32_t* sW = smem_u + 128 * 104; // 104 x 104 tf32 (k-major: sW[k*104+n])
    int tid = threadIdx.x;
    int row0 = blockIdx.x * 128;
    const uint4 z4 = make_uint4(0u, 0u, 0u, 0u);

    // ---- stage X: 2 threads/row, 13/12 independent LDG.128 each ----
    {
        int r = tid >> 1, half = tid & 1;
        int gr = row0 + r;
        uint32_t* drow = sX + r * 104;
        if (gr < N) {
            const float4* src = (const float4*)(X + (size_t)gr * 100);
#pragma unroll
            for (int t = 0; t < 13; t++) {
                int c4 = half * 13 + t;
                if (c4 < 25) {
                    float4 v = __ldg(src + c4);
                    uint4 u = make_uint4(f2tf32(v.x), f2tf32(v.y), f2tf32(v.z), f2tf32(v.w));
                    *(uint4*)(drow + c4 * 4) = u;
                }
            }
            if (half) *(uint4*)(drow + 100) = z4;  // pad cols 100..103
        } else {
#pragma unroll
            for (int t = 0; t < 13; t++) {
                int c4 = half * 13 + t;
                if (c4 < 25) *(uint4*)(drow + c4 * 4) = z4;
            }
            if (half) *(uint4*)(drow + 100) = z4;
        }
    }
    // ---- stage W: rows 0..99 data, rows 100..103 zero ----
    {
        int wr = tid >> 1, wh = tid & 1;
        if (wr < 100) {
            const float4* src = (const float4*)(W + wr * 100);
            uint32_t* drow = sW + wr * 104;
#pragma unroll
            for (int t = 0; t < 13; t++) {
                int c4 = wh * 13 + t;
                if (c4 < 25) {
                    float4 v = __ldg(src + c4);
                    uint4 u = make_uint4(f2tf32(v.x), f2tf32(v.y), f2tf32(v.z), f2tf32(v.w));
                    *(uint4*)(drow + c4 * 4) = u;
                }
            }
            if (wh) *(uint4*)(drow + 100) = z4;
        } else if (wr < 104) {
            uint32_t* drow = sW + wr * 104;
#pragma unroll
            for (int t = 0; t < 13; t++) {
                int c4 = wh * 13 + t;
                if (c4 < 26) *(uint4*)(drow + c4 * 4) = z4;
            }
        }
    }
    __syncthreads();

    int warp = tid >> 5, lane = tid & 31;
    int grp = lane >> 2, tig = lane & 3;
    const uint32_t* xw = sX + (warp * 16) * 104;

    float acc[13][4];
#pragma unroll
    for (int nt = 0; nt < 13; nt++)
#pragma unroll
        for (int i = 0; i < 4; i++) acc[nt][i] = 0.f;

    for (int kc = 0; kc < 13; kc++) {
        int k0 = kc * 8;
        uint32_t a0 = xw[grp * 104 + k0 + tig];
        uint32_t a1 = xw[(grp + 8) * 104 + k0 + tig];
        uint32_t a2 = xw[grp * 104 + k0 + tig + 4];
        uint32_t a3 = xw[(grp + 8) * 104 + k0 + tig + 4];
        const uint32_t* wr0 = sW + (k0 + tig) * 104 + grp;
        const uint32_t* wr1 = sW + (k0 + tig + 4) * 104 + grp;
#pragma unroll
        for (int nt = 0; nt < 13; nt++) {
            uint32_t b0 = wr0[nt * 8];
            uint32_t b1 = wr1[nt * 8];
            asm volatile(
                "mma.sync.aligned.m16n8k8.row.col.f32.tf32.tf32.f32 "
                "{%0,%1,%2,%3}, {%4,%5,%6,%7}, {%8,%9}, {%0,%1,%2,%3};"
                : "+f"(acc[nt][0]), "+f"(acc[nt][1]), "+f"(acc[nt][2]), "+f"(acc[nt][3])
                : "r"(a0), "r"(a1), "r"(a2), "r"(a3), "r"(b0), "r"(b1));
        }
    }

    int gr0 = row0 + warp * 16 + grp;
    int gr1 = gr0 + 8;
    float s0 = (gr0 < N) ? g_dinv[gr0] : 0.f;
    float s1 = (gr1 < N) ? g_dinv[gr1] : 0.f;
#pragma unroll
    for (int nt = 0; nt < 13; nt++) {
        int col = nt * 8 + 2 * tig;
        if (gr0 < N) {
            __half2 h = __floats2half2_rn(acc[nt][0] * s0, acc[nt][1] * s0);
            *(__half2*)(hs + (size_t)gr0 * 128 + col) = h;
        }
        if (gr1 < N) {
            __half2 h = __floats2half2_rn(acc[nt][2] * s1, acc[nt][3] * s1);
            *(__half2*)(hs + (size_t)gr1 * 128 + col) = h;
        }
    }
}

// ---------------- CSR agg ----------------
// TRANSFORM=1 (after layer0): acc = (dinv_i*rsqrt(norm2)) * sum + cb[k]
// TRANSFORM=0 (after layer1): acc = sum
template<int TRANSFORM>
__global__ void __launch_bounds__(256)
agg_kernel(const __half* __restrict__ hs, float* __restrict__ acc,
           const int* __restrict__ rowptr, const int* __restrict__ adj,
           const float* __restrict__ cb, int N) {
    int node = (blockIdx.x * 256 + threadIdx.x) >> 5;
    int lane = threadIdx.x & 31;
    if (node >= N) return;
    bool act = lane < 25;

    float4 sum = make_float4(0.f, 0.f, 0.f, 0.f);
    if (act) {
        uint2 raw = __ldg((const uint2*)(hs + (size_t)node * 128) + lane);
        float2 f0 = __half22float2(*(const __half2*)&raw.x);
        float2 f1 = __half22float2(*(const __half2*)&raw.y);
        sum.x = f0.x; sum.y = f0.y; sum.z = f1.x; sum.w = f1.y;
    }

    int beg = rowptr[node];
    int end = rowptr[node + 1];
    for (int base = beg; base < end; base += 32) {
        int idx = base + lane;
        int my = (idx < end) ? __ldg(adj + idx) : 0;
        int cnt = min(32, end - base);
#pragma unroll 8
        for (int j = 0; j < cnt; j++) {
            int s = __shfl_sync(0xffffffffu, my, j);
            if (act) {
                uint2 raw = __ldg((const uint2*)(hs + (size_t)s * 128) + lane);
                float2 f0 = __half22float2(*(const __half2*)&raw.x);
                float2 f1 = __half22float2(*(const __half2*)&raw.y);
                sum.x += f0.x; sum.y += f0.y; sum.z += f1.x; sum.w += f1.y;
            }
        }
    }
    if (act) {
        if (TRANSFORM) {
            float os = g_dinv[node] * rsqrtf(g_norm2);
            float4 b = __ldg((const float4*)cb + lane);
            sum.x = sum.x * os + b.x; sum.y = sum.y * os + b.y;
            sum.z = sum.z * os + b.z; sum.w = sum.w * os + b.w;
        }
        *((float4*)(acc + (size_t)node * 100) + lane) = sum;
    }
}

// ---------------- MLP head ----------------
__global__ void head_kernel(const float* __restrict__ acc, const float* __restrict__ bconv,
                            const float* __restrict__ W0, const float* __restrict__ b0,
                            const float* __restrict__ W1, const float* __restrict__ b1,
                            float* __restrict__ out, int N) {
    __shared__ float xs[64 * 101];
    __shared__ float w0s[1000];
    __shared__ float w1s[10];
    __shared__ float b0s[10];
    __shared__ float bcs[100];
    int tid = threadIdx.x;
    int base = blockIdx.x * 64;

    for (int i = tid; i < 1000; i += 128) w0s[i] = W0[i];
    if (tid < 10) { w1s[tid] = W1[tid]; b0s[tid] = b0[tid]; }
    if (tid < 100) bcs[tid] = bconv[tid];
    __syncthreads();

    for (int i = tid; i < 6400; i += 128) {
        int r = i / 100, k = i - r * 100;
        int g = base + r;
        xs[r * 101 + k] = (g < N) ? (g_dinv[g] * acc[(size_t)g * 100 + k] + bcs[k]) : 0.f;
    }
    __syncthreads();

    if (tid < 64) {
        int g = base + tid;
        if (g < N) {
            float y[10];
#pragma unroll
            for (int j = 0; j < 10; j++) y[j] = b0s[j];
            const float* xr = xs + tid * 101;
            for (int k = 0; k < 100; k++) {
                float xv = xr[k];
#pragma unroll
                for (int j = 0; j < 10; j++) y[j] += xv * w0s[k * 10 + j];
            }
            float o = b1[0];
#pragma unroll
            for (int j = 0; j < 10; j++) o += fmaxf(y[j], 0.f) * w1s[j];
            out[g] = o;
        }
    }
}

extern "C" void kernel_launch(void* const* d_in, const int* in_sizes, int n_in,
                              void* d_out, int out_size) {
    const float* x   = (const float*)d_in[0];
    const int*   ei  = (const int*)d_in[1];
    const float* W0  = (const float*)d_in[2];
    const float* cb0 = (const float*)d_in[3];
    const float* W1  = (const float*)d_in[4];
    const float* cb1 = (const float*)d_in[5];
    const float* lW0 = (const float*)d_in[6];
    const float* lb0 = (const float*)d_in[7];
    const float* lW1 = (const float*)d_in[8];
    const float* lb1 = (const float*)d_in[9];
    float* out = (float*)d_out;

    int N = in_sizes[0] / 100;
    int E = in_sizes[1] / 2;
    const int* src = ei;
    const int* dst = ei + E;

    size_t gemm_smem = (128 * 104 + 104 * 104) * sizeof(uint32_t);  // 96.5 KB -> 2 blocks/SM
    cudaFuncSetAttribute(gemm_mma_kernel,
                         cudaFuncAttributeMaxDynamicSharedMemorySize, (int)gemm_smem);

    __half* hs;
    float* acc;
    int *rowptr, *adj;
    cudaGetSymbolAddress((void**)&hs, g_hs);
    cudaGetSymbolAddress((void**)&acc, g_acc);
    cudaGetSymbolAddress((void**)&rowptr, g_rowptr);
    cudaGetSymbolAddress((void**)&adj, g_adj);

    // phase 0 (serial): degrees + norm partials, then dinv
    long n_elem = (long)N * 100;
    prephist_kernel<<<512, 256>>>(x, n_elem, dst, E);
    dinv_norm_kernel<<<(N + 255) / 256, 256>>>(N);

    // fork: branch A (CSR scan+fill) on s2  ||  branch B (gemm0) on default
    cudaStream_t s2;
    cudaStreamCreateWithFlags(&s2, cudaStreamNonBlocking);
    cudaEvent_t ev0, ev1;
    cudaEventCreateWithFlags(&ev0, cudaEventDisableTiming);
    cudaEventCreateWithFlags(&ev1, cudaEventDisableTiming);

    cudaEventRecord(ev0, 0);
    cudaStreamWaitEvent(s2, ev0, 0);

    int nscan = (N + 256) / 256;
    scan1_kernel<<<nscan, 256, 0, s2>>>(N);

    int gblocks = (N + 127) / 128;
    gemm_mma_kernel<<<gblocks, 256, gemm_smem>>>(x, W0, hs, N);

    scan2_kernel<<<1, 256, 0, s2>>>(nscan);
    scan3_kernel<<<nscan, 256, 0, s2>>>(N, E);
    fill_kernel<<<(E + 255) / 256, 256, 0, s2>>>(src, dst, E);
    cudaEventRecord(ev1, s2);

    cudaStreamWaitEvent(0, ev1, 0);  // join

    int ablocks = (N + 7) / 8;
    agg_kernel<1><<<ablocks, 256>>>(hs, acc, rowptr, adj, cb0, N);
    gemm_mma_kernel<<<gblocks, 256, gemm_smem>>>(acc, W1, hs, N);
    agg_kernel<0><<<ablocks, 256>>>(hs, acc, rowptr, adj, nullptr, N);
    head_kernel<<<(N + 63) / 64, 128>>>(acc, cb1, lW0, lb0, lW1, lb1, out, N);
}

// round 11
// speedup vs baseline: 2.9058x; 1.0734x over previous
#include <cuda_runtime.h>
#include <cuda_fp16.h>
#include <math.h>
#include <stdint.h>

// ---------------- scratch (no allocation allowed) ----------------
__device__ __half g_hs[6400000];   // 50000 x 128 halves (256B-aligned rows)
__device__ float  g_acc[5000000];  // 50000 x 100 fp32 (reused across layers)
__device__ float  g_dinv[50048];
__device__ int    g_cnt[50048];    // statically zero; re-zeroed by scan3 each call
__device__ int    g_rowptr[50049];
__device__ int    g_off[50049];
__device__ int    g_adj[800064];
__device__ int    g_bsum[256];
__device__ float  g_partials[512];
__device__ float  g_norm2;

// ---------------- ||x||^2 partial sums (s2, overlaps hist) ----------------
__global__ void sumsq_kernel(const float* __restrict__ x, long n) {
    int gs = gridDim.x * blockDim.x;
    float s = 0.f;
    for (long i = (long)blockIdx.x * blockDim.x + threadIdx.x; i < n; i += gs) {
        float v = x[i];
        s += v * v;
    }
    __shared__ float sm[256];
    sm[threadIdx.x] = s;
    __syncthreads();
    for (int o = 128; o > 0; o >>= 1) {
        if (threadIdx.x < o) sm[threadIdx.x] += sm[threadIdx.x + o];
        __syncthreads();
    }
    if (threadIdx.x == 0) g_partials[blockIdx.x] = sm[0];
}

__global__ void hist_kernel(const int* __restrict__ dst, int E) {
    int i = blockIdx.x * blockDim.x + threadIdx.x;
    if (i < E) atomicAdd(&g_cnt[dst[i]], 1);
}

__global__ void dinv_norm_kernel(int N) {
    if (blockIdx.x == 0) {
        __shared__ float fm[256];
        fm[threadIdx.x] = g_partials[threadIdx.x] + g_partials[threadIdx.x + 256];
        __syncthreads();
        for (int o = 128; o > 0; o >>= 1) {
            if (threadIdx.x < o) fm[threadIdx.x] += fm[threadIdx.x + o];
            __syncthreads();
        }
        if (threadIdx.x == 0) g_norm2 = fm[0];
    }
    int i = blockIdx.x * 256 + threadIdx.x;
    if (i < N) g_dinv[i] = rsqrtf((float)(g_cnt[i] + 1));
}

// ---------------- CSR build: multi-block scan chain ----------------
__global__ void scan1_kernel(int N) {
    __shared__ int sm[256];
    int node = blockIdx.x * 256 + threadIdx.x;
    int c = (node < N) ? g_cnt[node] : 0;
    sm[threadIdx.x] = c;
    __syncthreads();
    for (int o = 1; o < 256; o <<= 1) {
        int v = (threadIdx.x >= o) ? sm[threadIdx.x - o] : 0;
        __syncthreads();
        sm[threadIdx.x] += v;
        __syncthreads();
    }
    if (node <= N) g_rowptr[node] = sm[threadIdx.x] - c;
    if (threadIdx.x == 255) g_bsum[blockIdx.x] = sm[255];
}

__global__ void scan2_kernel(int nb) {
    __shared__ int sm[256];
    int c = (threadIdx.x < nb) ? g_bsum[threadIdx.x] : 0;
    sm[threadIdx.x] = c;
    __syncthreads();
    for (int o = 1; o < 256; o <<= 1) {
        int v = (threadIdx.x >= o) ? sm[threadIdx.x - o] : 0;
        __syncthreads();
        sm[threadIdx.x] += v;
        __syncthreads();
    }
    g_bsum[threadIdx.x] = sm[threadIdx.x] - c;
}

__global__ void scan3_kernel(int N, int E) {
    int node = blockIdx.x * 256 + threadIdx.x;
    if (node < N) {
        int r = g_rowptr[node] + g_bsum[blockIdx.x];
        g_rowptr[node] = r;
        g_off[node] = r;
        g_cnt[node] = 0;  // reset for next graph replay
    } else if (node == N) {
        g_rowptr[N] = E;
    }
}

__global__ void fill_kernel(const int* __restrict__ src, const int* __restrict__ dst, int E) {
    int i = blockIdx.x * blockDim.x + threadIdx.x;
    if (i < E) {
        int pos = atomicAdd(&g_off[dst[i]], 1);
        g_adj[pos] = src[i];
    }
}

// ---------------- fp16 tensor-core GEMM: hs = fp16(dinv[row] * (X @ W)) ----------------
// m16n8k16.row.col, f32 accum. smem rows padded to 120 halves (240B) -> bank-conflict-free.
// X tile 128x120 halves, W^T tile 104x120 halves. 7 k-chunks, 13 n-tiles.
#define SX_STRIDE 120
__global__ void __launch_bounds__(256, 3)
gemm_mma_kernel(const float* __restrict__ X, const float* __restrict__ W,
                __half* __restrict__ hs, int N) {
    extern __shared__ __half smem_h[];
    __half* sX = smem_h;                    // 128 x 120
    __half* sWt = smem_h + 128 * SX_STRIDE; // 104 x 120 (n-major, k contiguous)
    int tid = threadIdx.x;
    int row0 = blockIdx.x * 128;
    const uint2 z2 = make_uint2(0u, 0u);

    // zero W^T (including pads); filled after sync
    for (int i = tid; i < 104 * SX_STRIDE / 4; i += 256)
        ((uint2*)sWt)[i] = z2;

    // stage X: 2 threads/row, 13/12 independent LDG.128 -> half2 pairs
    {
        int r = tid >> 1, h = tid & 1;
        int gr = row0 + r;
        __half* drow = sX + r * SX_STRIDE;
        if (gr < N) {
            const float4* srcp = (const float4*)(X + (size_t)gr * 100);
#pragma unroll
            for (int t = 0; t < 13; t++) {
                int c4 = h * 13 + t;
                if (c4 < 25) {
                    float4 v = __ldg(srcp + c4);
                    __half2 lo = __floats2half2_rn(v.x, v.y);
                    __half2 hi = __floats2half2_rn(v.z, v.w);
                    uint2 u;
                    u.x = *(uint32_t*)&lo; u.y = *(uint32_t*)&hi;
                    *(uint2*)(drow + c4 * 4) = u;
                }
            }
        } else {
#pragma unroll
            for (int t = 0; t < 13; t++) {
                int c4 = h * 13 + t;
                if (c4 < 25) *(uint2*)(drow + c4 * 4) = z2;
            }
        }
        if (h) {  // pad cols 100..111
            *(uint2*)(drow + 100) = z2;
            *(uint2*)(drow + 104) = z2;
            *(uint2*)(drow + 108) = z2;
        }
    }
    __syncthreads();

    // stage W^T: read W[k][n] coalesced, scatter halves to sWt[n*120 + k]
    for (int i = tid; i < 10000; i += 256) {
        int k = i / 100, n = i - k * 100;
        sWt[n * SX_STRIDE + k] = __float2half_rn(__ldg(W + i));
    }
    __syncthreads();

    int warp = tid >> 5, lane = tid & 31;
    int grp = lane >> 2, tig = lane & 3;
    const __half* xw0 = sX + (warp * 16 + grp) * SX_STRIDE;
    const __half* xw1 = xw0 + 8 * SX_STRIDE;

    float acc[13][4];
#pragma unroll
    for (int nt = 0; nt < 13; nt++)
#pragma unroll
        for (int i = 0; i < 4; i++) acc[nt][i] = 0.f;

#pragma unroll
    for (int kc = 0; kc < 7; kc++) {
        int k0 = kc * 16;
        uint32_t a0 = *(const uint32_t*)(xw0 + k0 + 2 * tig);
        uint32_t a1 = *(const uint32_t*)(xw1 + k0 + 2 * tig);
        uint32_t a2 = *(const uint32_t*)(xw0 + k0 + 2 * tig + 8);
        uint32_t a3 = *(const uint32_t*)(xw1 + k0 + 2 * tig + 8);
        const __half* wb = sWt + grp * SX_STRIDE + k0 + 2 * tig;
#pragma unroll
        for (int nt = 0; nt < 13; nt++) {
            uint32_t b0 = *(const uint32_t*)(wb + nt * 8 * SX_STRIDE);
            uint32_t b1 = *(const uint32_t*)(wb + nt * 8 * SX_STRIDE + 8);
            asm volatile(
                "mma.sync.aligned.m16n8k16.row.col.f32.f16.f16.f32 "
                "{%0,%1,%2,%3}, {%4,%5,%6,%7}, {%8,%9}, {%0,%1,%2,%3};"
                : "+f"(acc[nt][0]), "+f"(acc[nt][1]), "+f"(acc[nt][2]), "+f"(acc[nt][3])
                : "r"(a0), "r"(a1), "r"(a2), "r"(a3), "r"(b0), "r"(b1));
        }
    }

    int gr0 = row0 + warp * 16 + grp;
    int gr1 = gr0 + 8;
    float s0 = (gr0 < N) ? g_dinv[gr0] : 0.f;
    float s1 = (gr1 < N) ? g_dinv[gr1] : 0.f;
#pragma unroll
    for (int nt = 0; nt < 13; nt++) {
        int col = nt * 8 + 2 * tig;
        if (gr0 < N) {
            __half2 h = __floats2half2_rn(acc[nt][0] * s0, acc[nt][1] * s0);
            *(__half2*)(hs + (size_t)gr0 * 128 + col) = h;
        }
        if (gr1 < N) {
            __half2 h = __floats2half2_rn(acc[nt][2] * s1, acc[nt][3] * s1);
            *(__half2*)(hs + (size_t)gr1 * 128 + col) = h;
        }
    }
}

// ---------------- CSR agg ----------------
// TRANSFORM=1 (after layer0): acc = (dinv_i*rsqrt(norm2)) * sum + cb[k]
// TRANSFORM=0 (after layer1): acc = sum
template<int TRANSFORM>
__global__ void __launch_bounds__(256)
agg_kernel(const __half* __restrict__ hs, float* __restrict__ acc,
           const int* __restrict__ rowptr, const int* __restrict__ adj,
           const float* __restrict__ cb, int N) {
    int node = (blockIdx.x * 256 + threadIdx.x) >> 5;
    int lane = threadIdx.x & 31;
    if (node >= N) return;
    bool act = lane < 25;

    float4 sum = make_float4(0.f, 0.f, 0.f, 0.f);
    if (act) {
        uint2 raw = __ldg((const uint2*)(hs + (size_t)node * 128) + lane);
        float2 f0 = __half22float2(*(const __half2*)&raw.x);
        float2 f1 = __half22float2(*(const __half2*)&raw.y);
        sum.x = f0.x; sum.y = f0.y; sum.z = f1.x; sum.w = f1.y;
    }

    int beg = rowptr[node];
    int end = rowptr[node + 1];
    for (int base = beg; base < end; base += 32) {
        int idx = base + lane;
        int my = (idx < end) ? __ldg(adj + idx) : 0;
        int cnt = min(32, end - base);
#pragma unroll 8
        for (int j = 0; j < cnt; j++) {
            int s = __shfl_sync(0xffffffffu, my, j);
            if (act) {
                uint2 raw = __ldg((const uint2*)(hs + (size_t)s * 128) + lane);
                float2 f0 = __half22float2(*(const __half2*)&raw.x);
                float2 f1 = __half22float2(*(const __half2*)&raw.y);
                sum.x += f0.x; sum.y += f0.y; sum.z += f1.x; sum.w += f1.y;
            }
        }
    }
    if (act) {
        if (TRANSFORM) {
            float os = g_dinv[node] * rsqrtf(g_norm2);
            float4 b = __ldg((const float4*)cb + lane);
            sum.x = sum.x * os + b.x; sum.y = sum.y * os + b.y;
            sum.z = sum.z * os + b.z; sum.w = sum.w * os + b.w;
        }
        *((float4*)(acc + (size_t)node * 100) + lane) = sum;
    }
}

// ---------------- MLP head ----------------
__global__ void head_kernel(const float* __restrict__ acc, const float* __restrict__ bconv,
                            const float* __restrict__ W0, const float* __restrict__ b0,
                            const float* __restrict__ W1, const float* __restrict__ b1,
                            float* __restrict__ out, int N) {
    __shared__ float xs[64 * 101];
    __shared__ float w0s[1000];
    __shared__ float w1s[10];
    __shared__ float b0s[10];
    __shared__ float bcs[100];
    int tid = threadIdx.x;
    int base = blockIdx.x * 64;

    for (int i = tid; i < 1000; i += 128) w0s[i] = W0[i];
    if (tid < 10) { w1s[tid] = W1[tid]; b0s[tid] = b0[tid]; }
    if (tid < 100) bcs[tid] = bconv[tid];
    __syncthreads();

    for (int i = tid; i < 6400; i += 128) {
        int r = i / 100, k = i - r * 100;
        int g = base + r;
        xs[r * 101 + k] = (g < N) ? (g_dinv[g] * acc[(size_t)g * 100 + k] + bcs[k]) : 0.f;
    }
    __syncthreads();

    if (tid < 64) {
        int g = base + tid;
        if (g < N) {
            float y[10];
#pragma unroll
            for (int j = 0; j < 10; j++) y[j] = b0s[j];
            const float* xr = xs + tid * 101;
            for (int k = 0; k < 100; k++) {
                float xv = xr[k];
#pragma unroll
                for (int j = 0; j < 10; j++) y[j] += xv * w0s[k * 10 + j];
            }
            float o = b1[0];
#pragma unroll
            for (int j = 0; j < 10; j++) o += fmaxf(y[j], 0.f) * w1s[j];
            out[g] = o;
        }
    }
}

extern "C" void kernel_launch(void* const* d_in, const int* in_sizes, int n_in,
                              void* d_out, int out_size) {
    const float* x   = (const float*)d_in[0];
    const int*   ei  = (const int*)d_in[1];
    const float* W0  = (const float*)d_in[2];
    const float* cb0 = (const float*)d_in[3];
    const float* W1  = (const float*)d_in[4];
    const float* cb1 = (const float*)d_in[5];
    const float* lW0 = (const float*)d_in[6];
    const float* lb0 = (const float*)d_in[7];
    const float* lW1 = (const float*)d_in[8];
    const float* lb1 = (const float*)d_in[9];
    float* out = (float*)d_out;

    int N = in_sizes[0] / 100;
    int E = in_sizes[1] / 2;
    const int* src = ei;
    const int* dst = ei + E;

    size_t gemm_smem = (128 + 104) * SX_STRIDE * sizeof(__half);  // 55.7 KB -> 3 blocks/SM
    cudaFuncSetAttribute(gemm_mma_kernel,
                         cudaFuncAttributeMaxDynamicSharedMemorySize, (int)gemm_smem);

    __half* hs;
    float* acc;
    int *rowptr, *adj;
    cudaGetSymbolAddress((void**)&hs, g_hs);
    cudaGetSymbolAddress((void**)&acc, g_acc);
    cudaGetSymbolAddress((void**)&rowptr, g_rowptr);
    cudaGetSymbolAddress((void**)&adj, g_adj);

    cudaStream_t s2;
    cudaStreamCreateWithFlags(&s2, cudaStreamNonBlocking);
    cudaEvent_t ev0, evH, evD, ev1;
    cudaEventCreateWithFlags(&ev0, cudaEventDisableTiming);
    cudaEventCreateWithFlags(&evH, cudaEventDisableTiming);
    cudaEventCreateWithFlags(&evD, cudaEventDisableTiming);
    cudaEventCreateWithFlags(&ev1, cudaEventDisableTiming);

    cudaEventRecord(ev0, 0);
    cudaStreamWaitEvent(s2, ev0, 0);

    // overlap: sumsq (s2) || hist (default)
    long n_elem = (long)N * 100;
    sumsq_kernel<<<512, 256, 0, s2>>>(x, n_elem);
    hist_kernel<<<(E + 255) / 256, 256>>>(dst, E);
    cudaEventRecord(evH, 0);
    cudaStreamWaitEvent(s2, evH, 0);

    // s2: dinv (needs cnt + partials) -> CSR scan chain -> fill
    dinv_norm_kernel<<<(50000 + 255) / 256, 256, 0, s2>>>(N);
    cudaEventRecord(evD, s2);
    int nscan = (N + 256) / 256;
    scan1_kernel<<<nscan, 256, 0, s2>>>(N);
    scan2_kernel<<<1, 256, 0, s2>>>(nscan);
    scan3_kernel<<<nscan, 256, 0, s2>>>(N, E);
    fill_kernel<<<(E + 255) / 256, 256, 0, s2>>>(src, dst, E);
    cudaEventRecord(ev1, s2);

    // default: gemm0 (needs dinv) overlaps scan chain + fill
    cudaStreamWaitEvent(0, evD, 0);
    int gblocks = (N + 127) / 128;
    gemm_mma_kernel<<<gblocks, 256, gemm_smem>>>(x, W0, hs, N);

    cudaStreamWaitEvent(0, ev1, 0);  // join

    int ablocks = (N + 7) / 8;
    agg_kernel<1><<<ablocks, 256>>>(hs, acc, rowptr, adj, cb0, N);
    gemm_mma_kernel<<<gblocks, 256, gemm_smem>>>(acc, W1, hs, N);
    agg_kernel<0><<<ablocks, 256>>>(hs, acc, rowptr, adj, nullptr, N);
    head_kernel<<<(N + 63) / 64, 128>>>(acc, cb1, lW0, lb0, lW1, lb1, out, N);
}

// round 12
// speedup vs baseline: 2.9568x; 1.0176x over previous
#include <cuda_runtime.h>
#include <cuda_fp16.h>
#include <math.h>
#include <stdint.h>

// ---------------- scratch (no allocation allowed) ----------------
__device__ __half g_hs[6400000];   // 50000 x 128 halves (256B-aligned rows)
__device__ float  g_acc[5000000];  // 50000 x 100 fp32 (layer-1 input)
__device__ float  g_dinv[50048];
__device__ int    g_cnt[50048];    // statically zero; re-zeroed by scan3 each call
__device__ int    g_rowptr[50049];
__device__ int    g_off[50049];
__device__ int    g_adj[800064];
__device__ int    g_bsum[256];
__device__ float  g_partials[512];
__device__ float  g_norm2;

// ---------------- ||x||^2 partial sums (s2, overlaps hist) ----------------
__global__ void sumsq_kernel(const float* __restrict__ x, long n) {
    int gs = gridDim.x * blockDim.x;
    float s = 0.f;
    for (long i = (long)blockIdx.x * blockDim.x + threadIdx.x; i < n; i += gs) {
        float v = x[i];
        s += v * v;
    }
    __shared__ float sm[256];
    sm[threadIdx.x] = s;
    __syncthreads();
    for (int o = 128; o > 0; o >>= 1) {
        if (threadIdx.x < o) sm[threadIdx.x] += sm[threadIdx.x + o];
        __syncthreads();
    }
    if (threadIdx.x == 0) g_partials[blockIdx.x] = sm[0];
}

__global__ void hist_kernel(const int* __restrict__ dst, int E) {
    int i = blockIdx.x * blockDim.x + threadIdx.x;
    if (i < E) atomicAdd(&g_cnt[dst[i]], 1);
}

// ---------------- scan1: block-local scan + dinv + norm2 finalize ----------------
__global__ void scan1_kernel(int N) {
    __shared__ int sm[256];
    int node = blockIdx.x * 256 + threadIdx.x;
    int c = (node < N) ? g_cnt[node] : 0;
    if (node < N) g_dinv[node] = rsqrtf((float)(c + 1));  // +1 self-loop
    if (blockIdx.x == 0) {
        __shared__ float fm[256];
        fm[threadIdx.x] = g_partials[threadIdx.x] + g_partials[threadIdx.x + 256];
        __syncthreads();
        for (int o = 128; o > 0; o >>= 1) {
            if (threadIdx.x < o) fm[threadIdx.x] += fm[threadIdx.x + o];
            __syncthreads();
        }
        if (threadIdx.x == 0) g_norm2 = fm[0];
    }
    sm[threadIdx.x] = c;
    __syncthreads();
    for (int o = 1; o < 256; o <<= 1) {
        int v = (threadIdx.x >= o) ? sm[threadIdx.x - o] : 0;
        __syncthreads();
        sm[threadIdx.x] += v;
        __syncthreads();
    }
    if (node <= N) g_rowptr[node] = sm[threadIdx.x] - c;
    if (threadIdx.x == 255) g_bsum[blockIdx.x] = sm[255];
}

__global__ void scan2_kernel(int nb) {
    __shared__ int sm[256];
    int c = (threadIdx.x < nb) ? g_bsum[threadIdx.x] : 0;
    sm[threadIdx.x] = c;
    __syncthreads();
    for (int o = 1; o < 256; o <<= 1) {
        int v = (threadIdx.x >= o) ? sm[threadIdx.x - o] : 0;
        __syncthreads();
        sm[threadIdx.x] += v;
        __syncthreads();
    }
    g_bsum[threadIdx.x] = sm[threadIdx.x] - c;
}

__global__ void scan3_kernel(int N, int E) {
    int node = blockIdx.x * 256 + threadIdx.x;
    if (node < N) {
        int r = g_rowptr[node] + g_bsum[blockIdx.x];
        g_rowptr[node] = r;
        g_off[node] = r;
        g_cnt[node] = 0;  // reset for next graph replay
    } else if (node == N) {
        g_rowptr[N] = E;
    }
}

__global__ void fill_kernel(const int* __restrict__ src, const int* __restrict__ dst, int E) {
    int i = blockIdx.x * blockDim.x + threadIdx.x;
    if (i < E) {
        int pos = atomicAdd(&g_off[dst[i]], 1);
        g_adj[pos] = src[i];
    }
}

// ---------------- fp16 tensor-core GEMM: hs = fp16(dinv[row] * (X @ W)) ----------------
#define SX_STRIDE 120
__global__ void __launch_bounds__(256, 3)
gemm_mma_kernel(const float* __restrict__ X, const float* __restrict__ W,
                __half* __restrict__ hs, int N) {
    extern __shared__ __half smem_h[];
    __half* sX = smem_h;                    // 128 x 120
    __half* sWt = smem_h + 128 * SX_STRIDE; // 104 x 120 (n-major, k contiguous)
    int tid = threadIdx.x;
    int row0 = blockIdx.x * 128;
    const uint2 z2 = make_uint2(0u, 0u);

    for (int i = tid; i < 104 * SX_STRIDE / 4; i += 256)
        ((uint2*)sWt)[i] = z2;

    {
        int r = tid >> 1, h = tid & 1;
        int gr = row0 + r;
        __half* drow = sX + r * SX_STRIDE;
        if (gr < N) {
            const float4* srcp = (const float4*)(X + (size_t)gr * 100);
#pragma unroll
            for (int t = 0; t < 13; t++) {
                int c4 = h * 13 + t;
                if (c4 < 25) {
                    float4 v = __ldg(srcp + c4);
                    __half2 lo = __floats2half2_rn(v.x, v.y);
                    __half2 hi = __floats2half2_rn(v.z, v.w);
                    uint2 u;
                    u.x = *(uint32_t*)&lo; u.y = *(uint32_t*)&hi;
                    *(uint2*)(drow + c4 * 4) = u;
                }
            }
        } else {
#pragma unroll
            for (int t = 0; t < 13; t++) {
                int c4 = h * 13 + t;
                if (c4 < 25) *(uint2*)(drow + c4 * 4) = z2;
            }
        }
        if (h) {
            *(uint2*)(drow + 100) = z2;
            *(uint2*)(drow + 104) = z2;
            *(uint2*)(drow + 108) = z2;
        }
    }
    __syncthreads();

    for (int i = tid; i < 10000; i += 256) {
        int k = i / 100, n = i - k * 100;
        sWt[n * SX_STRIDE + k] = __float2half_rn(__ldg(W + i));
    }
    __syncthreads();

    int warp = tid >> 5, lane = tid & 31;
    int grp = lane >> 2, tig = lane & 3;
    const __half* xw0 = sX + (warp * 16 + grp) * SX_STRIDE;
    const __half* xw1 = xw0 + 8 * SX_STRIDE;

    float acc[13][4];
#pragma unroll
    for (int nt = 0; nt < 13; nt++)
#pragma unroll
        for (int i = 0; i < 4; i++) acc[nt][i] = 0.f;

#pragma unroll
    for (int kc = 0; kc < 7; kc++) {
        int k0 = kc * 16;
        uint32_t a0 = *(const uint32_t*)(xw0 + k0 + 2 * tig);
        uint32_t a1 = *(const uint32_t*)(xw1 + k0 + 2 * tig);
        uint32_t a2 = *(const uint32_t*)(xw0 + k0 + 2 * tig + 8);
        uint32_t a3 = *(const uint32_t*)(xw1 + k0 + 2 * tig + 8);
        const __half* wb = sWt + grp * SX_STRIDE + k0 + 2 * tig;
#pragma unroll
        for (int nt = 0; nt < 13; nt++) {
            uint32_t b0 = *(const uint32_t*)(wb + nt * 8 * SX_STRIDE);
            uint32_t b1 = *(const uint32_t*)(wb + nt * 8 * SX_STRIDE + 8);
            asm volatile(
                "mma.sync.aligned.m16n8k16.row.col.f32.f16.f16.f32 "
                "{%0,%1,%2,%3}, {%4,%5,%6,%7}, {%8,%9}, {%0,%1,%2,%3};"
                : "+f"(acc[nt][0]), "+f"(acc[nt][1]), "+f"(acc[nt][2]), "+f"(acc[nt][3])
                : "r"(a0), "r"(a1), "r"(a2), "r"(a3), "r"(b0), "r"(b1));
        }
    }

    int gr0 = row0 + warp * 16 + grp;
    int gr1 = gr0 + 8;
    float s0 = (gr0 < N) ? g_dinv[gr0] : 0.f;
    float s1 = (gr1 < N) ? g_dinv[gr1] : 0.f;
#pragma unroll
    for (int nt = 0; nt < 13; nt++) {
        int col = nt * 8 + 2 * tig;
        if (gr0 < N) {
            __half2 h = __floats2half2_rn(acc[nt][0] * s0, acc[nt][1] * s0);
            *(__half2*)(hs + (size_t)gr0 * 128 + col) = h;
        }
        if (gr1 < N) {
            __half2 h = __floats2half2_rn(acc[nt][2] * s1, acc[nt][3] * s1);
            *(__half2*)(hs + (size_t)gr1 * 128 + col) = h;
        }
    }
}

// ---------------- agg after layer0: acc = (dinv_i*rsqrt(norm2))*sum + cb0 (fp32) ----------------
__global__ void __launch_bounds__(256)
agg_kernel(const __half* __restrict__ hs, float* __restrict__ acc,
           const int* __restrict__ rowptr, const int* __restrict__ adj,
           const float* __restrict__ cb, int N) {
    int node = (blockIdx.x * 256 + threadIdx.x) >> 5;
    int lane = threadIdx.x & 31;
    if (node >= N) return;
    bool act = lane < 25;

    float4 sum = make_float4(0.f, 0.f, 0.f, 0.f);
    if (act) {
        uint2 raw = __ldg((const uint2*)(hs + (size_t)node * 128) + lane);
        float2 f0 = __half22float2(*(const __half2*)&raw.x);
        float2 f1 = __half22float2(*(const __half2*)&raw.y);
        sum.x = f0.x; sum.y = f0.y; sum.z = f1.x; sum.w = f1.y;
    }

    int beg = rowptr[node];
    int end = rowptr[node + 1];
    for (int base = beg; base < end; base += 32) {
        int idx = base + lane;
        int my = (idx < end) ? __ldg(adj + idx) : 0;
        int cnt = min(32, end - base);
#pragma unroll 8
        for (int j = 0; j < cnt; j++) {
            int s = __shfl_sync(0xffffffffu, my, j);
            if (act) {
                uint2 raw = __ldg((const uint2*)(hs + (size_t)s * 128) + lane);
                float2 f0 = __half22float2(*(const __half2*)&raw.x);
                float2 f1 = __half22float2(*(const __half2*)&raw.y);
                sum.x += f0.x; sum.y += f0.y; sum.z += f1.x; sum.w += f1.y;
            }
        }
    }
    if (act) {
        float os = g_dinv[node] * rsqrtf(g_norm2);
        float4 b = __ldg((const float4*)cb + lane);
        sum.x = sum.x * os + b.x; sum.y = sum.y * os + b.y;
        sum.z = sum.z * os + b.z; sum.w = sum.w * os + b.w;
        *((float4*)(acc + (size_t)node * 100) + lane) = sum;
    }
}

// ---------------- fused agg after layer1 + MLP head ----------------
// x2 = dinv_i*sum + cb1; out[i] = relu(x2@W0+b0)@W1 + b1
__global__ void __launch_bounds__(256)
agg_head_kernel(const __half* __restrict__ hs,
                const int* __restrict__ rowptr, const int* __restrict__ adj,
                const float* __restrict__ cb,
                const float* __restrict__ W0, const float* __restrict__ b0,
                const float* __restrict__ W1, const float* __restrict__ b1,
                float* __restrict__ out, int N) {
    __shared__ float w0t[10 * 104];  // transposed W0: w0t[j*104+k] = W0[k*10+j]
    __shared__ float b0s[10];
    __shared__ float w1s[10];
    __shared__ float b1v;
    int tid = threadIdx.x;

    for (int i = tid; i < 1000; i += 256) {
        int k = i / 10, j = i - k * 10;
        w0t[j * 104 + k] = __ldg(W0 + i);
    }
    if (tid < 10) { b0s[tid] = __ldg(b0 + tid); w1s[tid] = __ldg(W1 + tid); }
    if (tid == 0) b1v = __ldg(b1);
    __syncthreads();

    int node = (blockIdx.x * 256 + tid) >> 5;
    int lane = tid & 31;
    if (node >= N) return;
    bool act = lane < 25;

    // ---- aggregation (proven loop) ----
    float4 sum = make_float4(0.f, 0.f, 0.f, 0.f);
    if (act) {
        uint2 raw = __ldg((const uint2*)(hs + (size_t)node * 128) + lane);
        float2 f0 = __half22float2(*(const __half2*)&raw.x);
        float2 f1 = __half22float2(*(const __half2*)&raw.y);
        sum.x = f0.x; sum.y = f0.y; sum.z = f1.x; sum.w = f1.y;
    }
    int beg = rowptr[node];
    int end = rowptr[node + 1];
    for (int base = beg; base < end; base += 32) {
        int idx = base + lane;
        int my = (idx < end) ? __ldg(adj + idx) : 0;
        int cnt = min(32, end - base);
#pragma unroll 8
        for (int j = 0; j < cnt; j++) {
            int s = __shfl_sync(0xffffffffu, my, j);
            if (act) {
                uint2 raw = __ldg((const uint2*)(hs + (size_t)s * 128) + lane);
                float2 f0 = __half22float2(*(const __half2*)&raw.x);
                float2 f1 = __half22float2(*(const __half2*)&raw.y);
                sum.x += f0.x; sum.y += f0.y; sum.z += f1.x; sum.w += f1.y;
            }
        }
    }

    // ---- x2 = dinv*sum + cb1 (lane owns cols 4*lane..4*lane+3) ----
    float4 x2 = make_float4(0.f, 0.f, 0.f, 0.f);
    if (act) {
        float di = g_dinv[node];
        float4 b = __ldg((const float4*)cb + lane);
        x2.x = di * sum.x + b.x; x2.y = di * sum.y + b.y;
        x2.z = di * sum.z + b.z; x2.w = di * sum.w + b.w;
    }

    // ---- head: p[j] = lane-partial of x2 . W0[:,j] (one LDS.128 per j) ----
    float p[10];
#pragma unroll
    for (int j = 0; j < 10; j++) {
        float4 w = make_float4(0.f, 0.f, 0.f, 0.f);
        if (act) w = *(const float4*)(w0t + j * 104 + 4 * lane);
        p[j] = x2.x * w.x + x2.y * w.y + x2.z * w.z + x2.w * w.w;
    }
#pragma unroll
    for (int j = 0; j < 10; j++) {
#pragma unroll
        for (int off = 16; off > 0; off >>= 1)
            p[j] += __shfl_xor_sync(0xffffffffu, p[j], off);
    }
    if (lane == 0) {
        float o = b1v;
#pragma unroll
        for (int j = 0; j < 10; j++) o += fmaxf(p[j] + b0s[j], 0.f) * w1s[j];
        out[node] = o;
    }
}

extern "C" void kernel_launch(void* const* d_in, const int* in_sizes, int n_in,
                              void* d_out, int out_size) {
    const float* x   = (const float*)d_in[0];
    const int*   ei  = (const int*)d_in[1];
    const float* W0  = (const float*)d_in[2];
    const float* cb0 = (const float*)d_in[3];
    const float* W1  = (const float*)d_in[4];
    const float* cb1 = (const float*)d_in[5];
    const float* lW0 = (const float*)d_in[6];
    const float* lb0 = (const float*)d_in[7];
    const float* lW1 = (const float*)d_in[8];
    const float* lb1 = (const float*)d_in[9];
    float* out = (float*)d_out;

    int N = in_sizes[0] / 100;
    int E = in_sizes[1] / 2;
    const int* src = ei;
    const int* dst = ei + E;

    size_t gemm_smem = (128 + 104) * SX_STRIDE * sizeof(__half);  // 55.7 KB -> 3 blocks/SM
    cudaFuncSetAttribute(gemm_mma_kernel,
                         cudaFuncAttributeMaxDynamicSharedMemorySize, (int)gemm_smem);

    __half* hs;
    float* acc;
    int *rowptr, *adj;
    cudaGetSymbolAddress((void**)&hs, g_hs);
    cudaGetSymbolAddress((void**)&acc, g_acc);
    cudaGetSymbolAddress((void**)&rowptr, g_rowptr);
    cudaGetSymbolAddress((void**)&adj, g_adj);

    cudaStream_t s2;
    cudaStreamCreateWithFlags(&s2, cudaStreamNonBlocking);
    cudaEvent_t ev0, evH, evD, ev1;
    cudaEventCreateWithFlags(&ev0, cudaEventDisableTiming);
    cudaEventCreateWithFlags(&evH, cudaEventDisableTiming);
    cudaEventCreateWithFlags(&evD, cudaEventDisableTiming);
    cudaEventCreateWithFlags(&ev1, cudaEventDisableTiming);

    cudaEventRecord(ev0, 0);
    cudaStreamWaitEvent(s2, ev0, 0);

    // overlap: sumsq (s2) || hist (default)
    long n_elem = (long)N * 100;
    sumsq_kernel<<<512, 256, 0, s2>>>(x, n_elem);
    hist_kernel<<<(E + 255) / 256, 256>>>(dst, E);
    cudaEventRecord(evH, 0);
    cudaStreamWaitEvent(s2, evH, 0);

    // s2: scan1 (local scan + dinv + norm2) -> scan2 -> scan3 -> fill
    int nscan = (N + 256) / 256;
    scan1_kernel<<<nscan, 256, 0, s2>>>(N);
    cudaEventRecord(evD, s2);
    scan2_kernel<<<1, 256, 0, s2>>>(nscan);
    scan3_kernel<<<nscan, 256, 0, s2>>>(N, E);
    fill_kernel<<<(E + 255) / 256, 256, 0, s2>>>(src, dst, E);
    cudaEventRecord(ev1, s2);

    // default: gemm0 (needs dinv) overlaps scan chain + fill
    cudaStreamWaitEvent(0, evD, 0);
    int gblocks = (N + 127) / 128;
    gemm_mma_kernel<<<gblocks, 256, gemm_smem>>>(x, W0, hs, N);

    cudaStreamWaitEvent(0, ev1, 0);  // join

    int ablocks = (N + 7) / 8;
    agg_kernel<<<ablocks, 256>>>(hs, acc, rowptr, adj, cb0, N);
    gemm_mma_kernel<<<gblocks, 256, gemm_smem>>>(acc, W1, hs, N);
    agg_head_kernel<<<ablocks, 256>>>(hs, rowptr, adj, cb1, lW0, lb0, lW1, lb1, out, N);
}